// round 1
// baseline (speedup 1.0000x reference)
#include <cuda_runtime.h>
#include <math.h>

#define NB 2
#define NS 2048
#define ND 1024
#define NH 16
#define NHD 64
#define MTOT (NB * NS)   // 4096

// Scratch (allocation-free rule: __device__ globals)
__device__ float g_q[NB * NH * NS * NHD];
__device__ float g_k[NB * NH * NS * NHD];
__device__ float g_v[NB * NH * NS * NHD];
__device__ float g_ctx[NB * NS * ND];

// ---------------------------------------------------------------------------
// 128x128x8 SGEMM tile body: C[128x128] = A[128 x 1024] * W[1024 x 128]
// 256 threads, 8x8 per-thread micro-tile, float4 global loads.
// ---------------------------------------------------------------------------
__device__ __forceinline__ void sgemm_tile(const float* __restrict__ A,
                                           const float* __restrict__ W,
                                           float (&c)[8][8]) {
    __shared__ float As[8][128];
    __shared__ float Bs[8][128];
    const int tid = threadIdx.x;
    const int tx = tid & 15, ty = tid >> 4;
    const int mBase = blockIdx.y * 128;
    const int nBase = blockIdx.x * 128;
    const int ar = tid >> 1, ac = (tid & 1) * 4;   // A: 128 rows x 8 cols
    const int br = tid >> 5, bc = (tid & 31) * 4;  // B: 8 rows x 128 cols

    for (int k0 = 0; k0 < ND; k0 += 8) {
        float4 av = *(const float4*)&A[(size_t)(mBase + ar) * ND + k0 + ac];
        As[ac + 0][ar] = av.x;
        As[ac + 1][ar] = av.y;
        As[ac + 2][ar] = av.z;
        As[ac + 3][ar] = av.w;
        *(float4*)&Bs[br][bc] =
            *(const float4*)&W[(size_t)(k0 + br) * ND + nBase + bc];
        __syncthreads();
#pragma unroll
        for (int k = 0; k < 8; k++) {
            float a[8], b[8];
#pragma unroll
            for (int i = 0; i < 8; i++) a[i] = As[k][ty * 8 + i];
#pragma unroll
            for (int j = 0; j < 8; j++) b[j] = Bs[k][tx * 8 + j];
#pragma unroll
            for (int i = 0; i < 8; i++)
#pragma unroll
                for (int j = 0; j < 8; j++) c[i][j] += a[i] * b[j];
        }
        __syncthreads();
    }
}

// QKV projection: writes to g_q/g_k/g_v in [B,H,S,HD] layout. gridDim.z = 3.
__global__ void __launch_bounds__(256)
qkv_proj_kernel(const float* __restrict__ x,
                const float* __restrict__ Wq, const float* __restrict__ bq,
                const float* __restrict__ Wk, const float* __restrict__ bk,
                const float* __restrict__ Wv, const float* __restrict__ bv) {
    const float* W;
    const float* bias;
    float* out;
    if (blockIdx.z == 0) { W = Wq; bias = bq; out = g_q; }
    else if (blockIdx.z == 1) { W = Wk; bias = bk; out = g_k; }
    else { W = Wv; bias = bv; out = g_v; }

    float c[8][8] = {};
    sgemm_tile(x, W, c);

    const int tx = threadIdx.x & 15, ty = threadIdx.x >> 4;
    const int mBase = blockIdx.y * 128, nBase = blockIdx.x * 128;
#pragma unroll
    for (int i = 0; i < 8; i++) {
        const int m = mBase + ty * 8 + i;
        const int b = m / NS;
        const int s = m % NS;
#pragma unroll
        for (int j = 0; j < 8; j++) {
            const int n = nBase + tx * 8 + j;
            const int h = n >> 6;
            const int hd = n & 63;
            out[(((b * NH + h) * NS + s) << 6) + hd] = c[i][j] + bias[n];
        }
    }
}

// Output projection: out = g_ctx @ Wo + bo  (plain [M,N] layout)
__global__ void __launch_bounds__(256)
out_proj_kernel(const float* __restrict__ Wo, const float* __restrict__ bo,
                float* __restrict__ out) {
    float c[8][8] = {};
    sgemm_tile(g_ctx, Wo, c);

    const int tx = threadIdx.x & 15, ty = threadIdx.x >> 4;
    const int mBase = blockIdx.y * 128, nBase = blockIdx.x * 128;
#pragma unroll
    for (int i = 0; i < 8; i++) {
        const int m = mBase + ty * 8 + i;
#pragma unroll
        for (int j = 0; j < 8; j++) {
            const int n = nBase + tx * 8 + j;
            out[(size_t)m * ND + n] = c[i][j] + bo[n];
        }
    }
}

// ---------------------------------------------------------------------------
// Flash attention: 64-query x 64-key tiles, HD=64, online softmax, causal.
// grid = (S/64, H, B), 256 threads, dynamic smem (padded rows -> no conflicts)
// ---------------------------------------------------------------------------
#define ATT_SMEM_FLOATS (4 * 64 * 65 + 3 * 64)
#define ATT_SMEM_BYTES (ATT_SMEM_FLOATS * 4)

__global__ void __launch_bounds__(256) flash_attn_kernel() {
    extern __shared__ float sm[];
    float(*Qs)[65] = (float(*)[65])sm;
    float(*Ks)[65] = (float(*)[65])(sm + 64 * 65);
    float(*Vs)[65] = (float(*)[65])(sm + 2 * 64 * 65);
    float(*Ps)[65] = (float(*)[65])(sm + 3 * 64 * 65);
    float* mrow = sm + 4 * 64 * 65;
    float* lrow = mrow + 64;
    float* arow = lrow + 64;

    const int tid = threadIdx.x;
    const int tx = tid & 15, ty = tid >> 4;
    const int qt = blockIdx.x, h = blockIdx.y, b = blockIdx.z;
    const int bhBase = ((b * NH + h) * NS) << 6;
    const float* Qg = g_q + bhBase;
    const float* Kg = g_k + bhBase;
    const float* Vg = g_v + bhBase;

    // Load Q tile, pre-scaled by 1/sqrt(64)=0.125
    for (int i = tid; i < 64 * 16; i += 256) {
        const int r = i >> 4, c4 = (i & 15) * 4;
        float4 v = *(const float4*)&Qg[((qt * 64 + r) << 6) + c4];
        Qs[r][c4 + 0] = v.x * 0.125f;
        Qs[r][c4 + 1] = v.y * 0.125f;
        Qs[r][c4 + 2] = v.z * 0.125f;
        Qs[r][c4 + 3] = v.w * 0.125f;
    }
    if (tid < 64) { mrow[tid] = -1e30f; lrow[tid] = 0.0f; }
    float o[4][4] = {};
    __syncthreads();

    for (int kt = 0; kt <= qt; kt++) {
        // Load K and V tiles
        for (int i = tid; i < 64 * 16; i += 256) {
            const int r = i >> 4, c4 = (i & 15) * 4;
            float4 kv = *(const float4*)&Kg[((kt * 64 + r) << 6) + c4];
            Ks[r][c4 + 0] = kv.x; Ks[r][c4 + 1] = kv.y;
            Ks[r][c4 + 2] = kv.z; Ks[r][c4 + 3] = kv.w;
            float4 vv = *(const float4*)&Vg[((kt * 64 + r) << 6) + c4];
            Vs[r][c4 + 0] = vv.x; Vs[r][c4 + 1] = vv.y;
            Vs[r][c4 + 2] = vv.z; Vs[r][c4 + 3] = vv.w;
        }
        __syncthreads();

        // S = (Q*scale) @ K^T  (4x4 micro-tile per thread)
        float s[4][4] = {};
#pragma unroll 8
        for (int k = 0; k < 64; k++) {
            float a[4], bb[4];
#pragma unroll
            for (int i = 0; i < 4; i++) a[i] = Qs[ty * 4 + i][k];
#pragma unroll
            for (int j = 0; j < 4; j++) bb[j] = Ks[tx * 4 + j][k];
#pragma unroll
            for (int i = 0; i < 4; i++)
#pragma unroll
                for (int j = 0; j < 4; j++) s[i][j] += a[i] * bb[j];
        }
        // Causal mask (only needed on the diagonal tile)
        if (kt == qt) {
#pragma unroll
            for (int i = 0; i < 4; i++)
#pragma unroll
                for (int j = 0; j < 4; j++)
                    if (tx * 4 + j > ty * 4 + i) s[i][j] = -1e30f;
        }
#pragma unroll
        for (int i = 0; i < 4; i++)
#pragma unroll
            for (int j = 0; j < 4; j++) Ps[ty * 4 + i][tx * 4 + j] = s[i][j];
        __syncthreads();

        // Online softmax row pass (one thread per query row)
        if (tid < 64) {
            const float mo = mrow[tid];
            float mx = mo;
#pragma unroll 8
            for (int c = 0; c < 64; c++) mx = fmaxf(mx, Ps[tid][c]);
            const float al = __expf(mo - mx);
            float sum = 0.0f;
#pragma unroll 8
            for (int c = 0; c < 64; c++) {
                const float p = __expf(Ps[tid][c] - mx);
                Ps[tid][c] = p;
                sum += p;
            }
            lrow[tid] = lrow[tid] * al + sum;
            mrow[tid] = mx;
            arow[tid] = al;
        }
        __syncthreads();

        // O = O*alpha + P @ V
        float al[4];
#pragma unroll
        for (int i = 0; i < 4; i++) al[i] = arow[ty * 4 + i];
#pragma unroll
        for (int i = 0; i < 4; i++)
#pragma unroll
            for (int j = 0; j < 4; j++) o[i][j] *= al[i];
#pragma unroll 8
        for (int k = 0; k < 64; k++) {
            float p[4], vv[4];
#pragma unroll
            for (int i = 0; i < 4; i++) p[i] = Ps[ty * 4 + i][k];
#pragma unroll
            for (int j = 0; j < 4; j++) vv[j] = Vs[k][tx * 4 + j];
#pragma unroll
            for (int i = 0; i < 4; i++)
#pragma unroll
                for (int j = 0; j < 4; j++) o[i][j] += p[i] * vv[j];
        }
        __syncthreads();
    }

    // Normalize and write ctx in [B,S,D] layout
    float inv[4];
#pragma unroll
    for (int i = 0; i < 4; i++) inv[i] = 1.0f / lrow[ty * 4 + i];
#pragma unroll
    for (int i = 0; i < 4; i++) {
        const int q = qt * 64 + ty * 4 + i;
#pragma unroll
        for (int j = 0; j < 4; j++)
            g_ctx[(size_t)(b * NS + q) * ND + (h << 6) + tx * 4 + j] =
                o[i][j] * inv[i];
    }
}

extern "C" void kernel_launch(void* const* d_in, const int* in_sizes, int n_in,
                              void* d_out, int out_size) {
    const float* x = (const float*)d_in[0];
    const float* Wq = (const float*)d_in[1];
    const float* bq = (const float*)d_in[2];
    const float* Wk = (const float*)d_in[3];
    const float* bk = (const float*)d_in[4];
    const float* Wv = (const float*)d_in[5];
    const float* bv = (const float*)d_in[6];
    const float* Wo = (const float*)d_in[7];
    const float* bo = (const float*)d_in[8];
    float* out = (float*)d_out;

    cudaFuncSetAttribute(flash_attn_kernel,
                         cudaFuncAttributeMaxDynamicSharedMemorySize,
                         ATT_SMEM_BYTES);

    dim3 g1(ND / 128, MTOT / 128, 3);
    qkv_proj_kernel<<<g1, 256>>>(x, Wq, bq, Wk, bk, Wv, bv);

    dim3 g2(NS / 64, NH, NB);
    flash_attn_kernel<<<g2, 256, ATT_SMEM_BYTES>>>();

    dim3 g3(ND / 128, MTOT / 128);
    out_proj_kernel<<<g3, 256>>>(Wo, bo, out);
}

// round 3
// speedup vs baseline: 1.9550x; 1.9550x over previous
#include <cuda_runtime.h>
#include <math.h>

#define NB 2
#define NS 2048
#define ND 1024
#define NH 16
#define NHD 64
#define MTOT (NB * NS)   // 4096

// Scratch (allocation-free rule: __device__ globals)
__device__ float g_q[NB * NH * NS * NHD];
__device__ float g_k[NB * NH * NS * NHD];
__device__ float g_v[NB * NH * NS * NHD];
__device__ float g_ctx[NB * NS * ND];

// ---------------------------------------------------------------------------
// helpers
// ---------------------------------------------------------------------------
__device__ __forceinline__ float f2tf32(float x) {
    unsigned r;
    asm("cvt.rna.tf32.f32 %0, %1;" : "=r"(r) : "f"(x));
    return __uint_as_float(r);
}

__device__ __forceinline__ void mma_tf32(float (&c)[4], unsigned a0, unsigned a1,
                                         unsigned a2, unsigned a3, unsigned b0,
                                         unsigned b1) {
    asm volatile(
        "mma.sync.aligned.m16n8k8.row.col.f32.tf32.tf32.f32 "
        "{%0,%1,%2,%3}, {%4,%5,%6,%7}, {%8,%9}, {%0,%1,%2,%3};\n"
        : "+f"(c[0]), "+f"(c[1]), "+f"(c[2]), "+f"(c[3])
        : "r"(a0), "r"(a1), "r"(a2), "r"(a3), "r"(b0), "r"(b1));
}

// interleave k within 8-blocks so fragment pairs (k, k+4) are adjacent
__device__ __forceinline__ int permk(int c) {
    return (c & ~7) | ((c & 3) << 1) | ((c >> 2) & 1);
}

// ---------------------------------------------------------------------------
// 128x128x32 TF32 tensor-core GEMM tile: C = A[128x1024] @ W[1024x128]
// 256 threads, 8 warps in 4(M) x 2(N); warp tile 32x64 = 2x8 m16n8k8 atoms.
// ---------------------------------------------------------------------------
__device__ __forceinline__ void sgemm_mma(const float* __restrict__ A,
                                          const float* __restrict__ W,
                                          float (&acc)[2][8][4]) {
    __shared__ float As[128][36];   // [m][perm(k)], k-pairs interleaved
    __shared__ float Bs[32][132];   // [k][n] plain, padded stride

    const int tid = threadIdx.x;
    const int lane = tid & 31;
    const int wid = tid >> 5;
    const int warpM = wid >> 1;   // 0..3
    const int warpN = wid & 1;    // 0..1
    const int gid = lane >> 2;    // 0..7
    const int tig = lane & 3;     // 0..3
    const int mBase = blockIdx.y * 128;
    const int nBase = blockIdx.x * 128;

    for (int k0 = 0; k0 < ND; k0 += 32) {
#pragma unroll
        for (int i = 0; i < 4; i++) {
            const int f4 = tid + i * 256;
            const int m = f4 >> 3, c4 = (f4 & 7) * 4;
            float4 v = *(const float4*)&A[(size_t)(mBase + m) * ND + k0 + c4];
            As[m][permk(c4 + 0)] = f2tf32(v.x);
            As[m][permk(c4 + 1)] = f2tf32(v.y);
            As[m][permk(c4 + 2)] = f2tf32(v.z);
            As[m][permk(c4 + 3)] = f2tf32(v.w);
        }
#pragma unroll
        for (int i = 0; i < 4; i++) {
            const int f4 = tid + i * 256;
            const int kk = f4 >> 5, n4 = (f4 & 31) * 4;
            float4 v = *(const float4*)&W[(size_t)(k0 + kk) * ND + nBase + n4];
            Bs[kk][n4 + 0] = f2tf32(v.x);
            Bs[kk][n4 + 1] = f2tf32(v.y);
            Bs[kk][n4 + 2] = f2tf32(v.z);
            Bs[kk][n4 + 3] = f2tf32(v.w);
        }
        __syncthreads();

#pragma unroll
        for (int ks = 0; ks < 32; ks += 8) {
            unsigned bf[8][2];
#pragma unroll
            for (int nt = 0; nt < 8; nt++) {
                const int n = warpN * 64 + nt * 8 + gid;
                bf[nt][0] = __float_as_uint(Bs[ks + tig][n]);
                bf[nt][1] = __float_as_uint(Bs[ks + tig + 4][n]);
            }
#pragma unroll
            for (int mt = 0; mt < 2; mt++) {
                const int m = warpM * 32 + mt * 16;
                float2 lo = *(const float2*)&As[m + gid][ks + 2 * tig];
                float2 hi = *(const float2*)&As[m + gid + 8][ks + 2 * tig];
                const unsigned a0 = __float_as_uint(lo.x);
                const unsigned a1 = __float_as_uint(hi.x);
                const unsigned a2 = __float_as_uint(lo.y);
                const unsigned a3 = __float_as_uint(hi.y);
#pragma unroll
                for (int nt = 0; nt < 8; nt++)
                    mma_tf32(acc[mt][nt], a0, a1, a2, a3, bf[nt][0], bf[nt][1]);
            }
        }
        __syncthreads();
    }
}

// QKV projection: writes to g_q/g_k/g_v in [B,H,S,HD] layout. gridDim.z = 3.
__global__ void __launch_bounds__(256, 2)
qkv_proj_kernel(const float* __restrict__ x,
                const float* __restrict__ Wq, const float* __restrict__ bq,
                const float* __restrict__ Wk, const float* __restrict__ bk,
                const float* __restrict__ Wv, const float* __restrict__ bv) {
    const float* W;
    const float* bias;
    float* out;
    if (blockIdx.z == 0) { W = Wq; bias = bq; out = g_q; }
    else if (blockIdx.z == 1) { W = Wk; bias = bk; out = g_k; }
    else { W = Wv; bias = bv; out = g_v; }

    float acc[2][8][4] = {};
    sgemm_mma(x, W, acc);

    const int lane = threadIdx.x & 31;
    const int wid = threadIdx.x >> 5;
    const int warpM = wid >> 1, warpN = wid & 1;
    const int gid = lane >> 2, tig = lane & 3;
    const int mBase = blockIdx.y * 128, nBase = blockIdx.x * 128;

#pragma unroll
    for (int mt = 0; mt < 2; mt++) {
#pragma unroll
        for (int nt = 0; nt < 8; nt++) {
            const int c = nBase + warpN * 64 + nt * 8 + tig * 2;
            const int h = c >> 6, hd = c & 63;
            const float b0v = bias[c], b1v = bias[c + 1];
#pragma unroll
            for (int half = 0; half < 2; half++) {
                const int r = mBase + warpM * 32 + mt * 16 + gid + half * 8;
                const int b = r >> 11, s = r & 2047;
                float2 val;
                val.x = acc[mt][nt][half * 2 + 0] + b0v;
                val.y = acc[mt][nt][half * 2 + 1] + b1v;
                *(float2*)&out[(((b * NH + h) * NS + s) << 6) + hd] = val;
            }
        }
    }
}

// Output projection: out = g_ctx @ Wo + bo  (plain [M,N] layout)
__global__ void __launch_bounds__(256, 2)
out_proj_kernel(const float* __restrict__ Wo, const float* __restrict__ bo,
                float* __restrict__ out) {
    float acc[2][8][4] = {};
    sgemm_mma(g_ctx, Wo, acc);

    const int lane = threadIdx.x & 31;
    const int wid = threadIdx.x >> 5;
    const int warpM = wid >> 1, warpN = wid & 1;
    const int gid = lane >> 2, tig = lane & 3;
    const int mBase = blockIdx.y * 128, nBase = blockIdx.x * 128;

#pragma unroll
    for (int mt = 0; mt < 2; mt++) {
#pragma unroll
        for (int nt = 0; nt < 8; nt++) {
            const int c = nBase + warpN * 64 + nt * 8 + tig * 2;
            const float b0v = bo[c], b1v = bo[c + 1];
#pragma unroll
            for (int half = 0; half < 2; half++) {
                const int r = mBase + warpM * 32 + mt * 16 + gid + half * 8;
                float2 val;
                val.x = acc[mt][nt][half * 2 + 0] + b0v;
                val.y = acc[mt][nt][half * 2 + 1] + b1v;
                *(float2*)&out[(size_t)r * ND + c] = val;
            }
        }
    }
}

// ---------------------------------------------------------------------------
// Flash attention with tf32 mma: 64q x 64k tiles, HD=64, online softmax.
// 256 threads = 8 warps in 4(M) x 2(N). grid = (S/64, H, B).
// Dynamic smem layout (floats):
//   Qs[64][66] interleaved | Ks[64][66] interleaved | Vs[64][68] plain |
//   Ps[64][66] interleaved | mrow[64] | lrow[64] | arow[64]
// ---------------------------------------------------------------------------
#define QS_OFF 0
#define KS_OFF (64 * 66)
#define VS_OFF (KS_OFF + 64 * 66)
#define PS_OFF (VS_OFF + 64 * 68)
#define MR_OFF (PS_OFF + 64 * 66)
#define LR_OFF (MR_OFF + 64)
#define AR_OFF (LR_OFF + 64)
#define ATT_SMEM_FLOATS (AR_OFF + 64)
#define ATT_SMEM_BYTES (ATT_SMEM_FLOATS * 4)

__global__ void __launch_bounds__(256, 2) flash_attn_kernel() {
    extern __shared__ float sm[];
    float* Qs = sm + QS_OFF;   // stride 66, perm(k)
    float* Ks = sm + KS_OFF;   // stride 66, perm(k)  [key][hd]
    float* Vs = sm + VS_OFF;   // stride 68, plain    [key][hd]
    float* Ps = sm + PS_OFF;   // stride 66, perm(key)
    float* mrow = sm + MR_OFF;
    float* lrow = sm + LR_OFF;
    float* arow = sm + AR_OFF;

    const int tid = threadIdx.x;
    const int lane = tid & 31;
    const int wid = tid >> 5;
    const int warpM = wid >> 1;  // 0..3 -> 16 query rows each
    const int warpN = wid & 1;   // 0..1 -> 32 cols each
    const int gid = lane >> 2, tig = lane & 3;

    const int qt = blockIdx.x, h = blockIdx.y, b = blockIdx.z;
    const int bhBase = ((b * NH + h) * NS) << 6;
    const float* Qg = g_q + bhBase;
    const float* Kg = g_k + bhBase;
    const float* Vg = g_v + bhBase;

    // Load Q tile, pre-scaled by 1/sqrt(64)=0.125, tf32-rounded, interleaved
#pragma unroll
    for (int i = 0; i < 4; i++) {
        const int f4 = tid + i * 256;
        const int r = f4 >> 4, c4 = (f4 & 15) * 4;
        float4 v = *(const float4*)&Qg[((qt * 64 + r) << 6) + c4];
        Qs[r * 66 + permk(c4 + 0)] = f2tf32(v.x * 0.125f);
        Qs[r * 66 + permk(c4 + 1)] = f2tf32(v.y * 0.125f);
        Qs[r * 66 + permk(c4 + 2)] = f2tf32(v.z * 0.125f);
        Qs[r * 66 + permk(c4 + 3)] = f2tf32(v.w * 0.125f);
    }
    if (tid < 64) { mrow[tid] = -1e30f; lrow[tid] = 0.0f; }
    float o[4][4] = {};
    __syncthreads();

    for (int kt = 0; kt <= qt; kt++) {
        // Load K (interleaved) and V (plain), tf32-rounded
#pragma unroll
        for (int i = 0; i < 4; i++) {
            const int f4 = tid + i * 256;
            const int r = f4 >> 4, c4 = (f4 & 15) * 4;
            float4 kv = *(const float4*)&Kg[((kt * 64 + r) << 6) + c4];
            Ks[r * 66 + permk(c4 + 0)] = f2tf32(kv.x);
            Ks[r * 66 + permk(c4 + 1)] = f2tf32(kv.y);
            Ks[r * 66 + permk(c4 + 2)] = f2tf32(kv.z);
            Ks[r * 66 + permk(c4 + 3)] = f2tf32(kv.w);
            float4 vv = *(const float4*)&Vg[((kt * 64 + r) << 6) + c4];
            Vs[r * 68 + c4 + 0] = f2tf32(vv.x);
            Vs[r * 68 + c4 + 1] = f2tf32(vv.y);
            Vs[r * 68 + c4 + 2] = f2tf32(vv.z);
            Vs[r * 68 + c4 + 3] = f2tf32(vv.w);
        }
        __syncthreads();

        // S = Q @ K^T : each warp 16(rows) x 32(cols) = 4 n-tiles, 8 k-steps
        float s[4][4] = {};
        const int mrowBase = warpM * 16;
#pragma unroll
        for (int kb = 0; kb < 64; kb += 8) {
            float2 lo = *(const float2*)&Qs[(mrowBase + gid) * 66 + kb + 2 * tig];
            float2 hi = *(const float2*)&Qs[(mrowBase + gid + 8) * 66 + kb + 2 * tig];
            const unsigned a0 = __float_as_uint(lo.x);
            const unsigned a1 = __float_as_uint(hi.x);
            const unsigned a2 = __float_as_uint(lo.y);
            const unsigned a3 = __float_as_uint(hi.y);
#pragma unroll
            for (int nt = 0; nt < 4; nt++) {
                const int key = warpN * 32 + nt * 8 + gid;
                float2 bb = *(const float2*)&Ks[key * 66 + kb + 2 * tig];
                mma_tf32(s[nt], a0, a1, a2, a3, __float_as_uint(bb.x),
                         __float_as_uint(bb.y));
            }
        }

        // Store raw scores to Ps (perm along key), apply causal mask on diag tile
#pragma unroll
        for (int nt = 0; nt < 4; nt++) {
            const int col = warpN * 32 + nt * 8 + tig * 2;
#pragma unroll
            for (int half = 0; half < 2; half++) {
                const int row = mrowBase + gid + half * 8;
                float v0 = s[nt][half * 2 + 0];
                float v1 = s[nt][half * 2 + 1];
                if (kt == qt) {
                    if (col > row) v0 = -1e30f;
                    if (col + 1 > row) v1 = -1e30f;
                }
                Ps[row * 66 + permk(col)] = v0;
                Ps[row * 66 + permk(col + 1)] = v1;
            }
        }
        __syncthreads();

        // Online softmax: 4 threads per row, shfl reduce within quad
        {
            const int r = tid >> 2, sub = tid & 3;
            float mx = -1e30f;
#pragma unroll
            for (int i = 0; i < 16; i++)
                mx = fmaxf(mx, Ps[r * 66 + sub * 16 + i]);
            mx = fmaxf(mx, __shfl_xor_sync(0xffffffffu, mx, 1));
            mx = fmaxf(mx, __shfl_xor_sync(0xffffffffu, mx, 2));
            const float mold = mrow[r];
            const float mnew = fmaxf(mold, mx);
            const float al = __expf(mold - mnew);
            float sum = 0.0f;
#pragma unroll
            for (int i = 0; i < 16; i++) {
                const float p = __expf(Ps[r * 66 + sub * 16 + i] - mnew);
                Ps[r * 66 + sub * 16 + i] = f2tf32(p);
                sum += p;
            }
            sum += __shfl_xor_sync(0xffffffffu, sum, 1);
            sum += __shfl_xor_sync(0xffffffffu, sum, 2);
            if (sub == 0) {
                lrow[r] = lrow[r] * al + sum;
                mrow[r] = mnew;
                arow[r] = al;
            }
        }
        __syncthreads();

        // O = O*alpha + P @ V
        const float a0r = arow[mrowBase + gid];
        const float a1r = arow[mrowBase + gid + 8];
#pragma unroll
        for (int nt = 0; nt < 4; nt++) {
            o[nt][0] *= a0r;
            o[nt][1] *= a0r;
            o[nt][2] *= a1r;
            o[nt][3] *= a1r;
        }
#pragma unroll
        for (int kb = 0; kb < 64; kb += 8) {
            float2 lo = *(const float2*)&Ps[(mrowBase + gid) * 66 + kb + 2 * tig];
            float2 hi = *(const float2*)&Ps[(mrowBase + gid + 8) * 66 + kb + 2 * tig];
            const unsigned a0 = __float_as_uint(lo.x);
            const unsigned a1 = __float_as_uint(hi.x);
            const unsigned a2 = __float_as_uint(lo.y);
            const unsigned a3 = __float_as_uint(hi.y);
#pragma unroll
            for (int nt = 0; nt < 4; nt++) {
                const int hd = warpN * 32 + nt * 8 + gid;
                const unsigned b0 = __float_as_uint(Vs[(kb + tig) * 68 + hd]);
                const unsigned b1 = __float_as_uint(Vs[(kb + tig + 4) * 68 + hd]);
                mma_tf32(o[nt], a0, a1, a2, a3, b0, b1);
            }
        }
        __syncthreads();
    }

    // Normalize and write ctx in [B,S,D] layout
    const float i0 = 1.0f / lrow[warpM * 16 + gid];
    const float i1 = 1.0f / lrow[warpM * 16 + gid + 8];
#pragma unroll
    for (int nt = 0; nt < 4; nt++) {
        const int col = (h << 6) + warpN * 32 + nt * 8 + tig * 2;
        {
            const int q = qt * 64 + warpM * 16 + gid;
            float2 val = {o[nt][0] * i0, o[nt][1] * i0};
            *(float2*)&g_ctx[(size_t)(b * NS + q) * ND + col] = val;
        }
        {
            const int q = qt * 64 + warpM * 16 + gid + 8;
            float2 val = {o[nt][2] * i1, o[nt][3] * i1};
            *(float2*)&g_ctx[(size_t)(b * NS + q) * ND + col] = val;
        }
    }
}

extern "C" void kernel_launch(void* const* d_in, const int* in_sizes, int n_in,
                              void* d_out, int out_size) {
    const float* x = (const float*)d_in[0];
    const float* Wq = (const float*)d_in[1];
    const float* bq = (const float*)d_in[2];
    const float* Wk = (const float*)d_in[3];
    const float* bk = (const float*)d_in[4];
    const float* Wv = (const float*)d_in[5];
    const float* bv = (const float*)d_in[6];
    const float* Wo = (const float*)d_in[7];
    const float* bo = (const float*)d_in[8];
    float* out = (float*)d_out;

    cudaFuncSetAttribute(flash_attn_kernel,
                         cudaFuncAttributeMaxDynamicSharedMemorySize,
                         ATT_SMEM_BYTES);

    dim3 g1(ND / 128, MTOT / 128, 3);
    qkv_proj_kernel<<<g1, 256>>>(x, Wq, bq, Wk, bk, Wv, bv);

    dim3 g2(NS / 64, NH, NB);
    flash_attn_kernel<<<g2, 256, ATT_SMEM_BYTES>>>();

    dim3 g3(ND / 128, MTOT / 128);
    out_proj_kernel<<<g3, 256>>>(Wo, bo, out);
}

// round 4
// speedup vs baseline: 3.0465x; 1.5583x over previous
#include <cuda_runtime.h>
#include <math.h>

#define NB 2
#define NS 2048
#define ND 1024
#define NH 16
#define NHD 64
#define MTOT (NB * NS)   // 4096

// Scratch (allocation-free rule: __device__ globals)
__device__ float g_q[NB * NH * NS * NHD];
__device__ float g_k[NB * NH * NS * NHD];
__device__ float g_v[NB * NH * NS * NHD];
__device__ float g_ctx[NB * NS * ND];

// ---------------------------------------------------------------------------
// helpers
// ---------------------------------------------------------------------------
__device__ __forceinline__ float f2tf32(float x) {
    unsigned r;
    asm("cvt.rna.tf32.f32 %0, %1;" : "=r"(r) : "f"(x));
    return __uint_as_float(r);
}

__device__ __forceinline__ void mma_tf32(float (&c)[4], unsigned a0, unsigned a1,
                                         unsigned a2, unsigned a3, unsigned b0,
                                         unsigned b1) {
    asm volatile(
        "mma.sync.aligned.m16n8k8.row.col.f32.tf32.tf32.f32 "
        "{%0,%1,%2,%3}, {%4,%5,%6,%7}, {%8,%9}, {%0,%1,%2,%3};\n"
        : "+f"(c[0]), "+f"(c[1]), "+f"(c[2]), "+f"(c[3])
        : "r"(a0), "r"(a1), "r"(a2), "r"(a3), "r"(b0), "r"(b1));
}

// interleave k within 8-blocks so fragment pairs (k, k+4) are adjacent
__device__ __forceinline__ int permk(int c) {
    return (c & ~7) | ((c & 3) << 1) | ((c >> 2) & 1);
}

// ---------------------------------------------------------------------------
// 128x128x32 TF32 tensor-core GEMM tile: C = A[128x1024] @ W[1024x128]
// (unchanged from round 3 — known good)
// ---------------------------------------------------------------------------
__device__ __forceinline__ void sgemm_mma(const float* __restrict__ A,
                                          const float* __restrict__ W,
                                          float (&acc)[2][8][4]) {
    __shared__ float As[128][36];   // [m][perm(k)], k-pairs interleaved
    __shared__ float Bs[32][132];   // [k][n] plain, padded stride

    const int tid = threadIdx.x;
    const int lane = tid & 31;
    const int wid = tid >> 5;
    const int warpM = wid >> 1;   // 0..3
    const int warpN = wid & 1;    // 0..1
    const int gid = lane >> 2;    // 0..7
    const int tig = lane & 3;     // 0..3
    const int mBase = blockIdx.y * 128;
    const int nBase = blockIdx.x * 128;

    for (int k0 = 0; k0 < ND; k0 += 32) {
#pragma unroll
        for (int i = 0; i < 4; i++) {
            const int f4 = tid + i * 256;
            const int m = f4 >> 3, c4 = (f4 & 7) * 4;
            float4 v = *(const float4*)&A[(size_t)(mBase + m) * ND + k0 + c4];
            As[m][permk(c4 + 0)] = f2tf32(v.x);
            As[m][permk(c4 + 1)] = f2tf32(v.y);
            As[m][permk(c4 + 2)] = f2tf32(v.z);
            As[m][permk(c4 + 3)] = f2tf32(v.w);
        }
#pragma unroll
        for (int i = 0; i < 4; i++) {
            const int f4 = tid + i * 256;
            const int kk = f4 >> 5, n4 = (f4 & 31) * 4;
            float4 v = *(const float4*)&W[(size_t)(k0 + kk) * ND + nBase + n4];
            Bs[kk][n4 + 0] = f2tf32(v.x);
            Bs[kk][n4 + 1] = f2tf32(v.y);
            Bs[kk][n4 + 2] = f2tf32(v.z);
            Bs[kk][n4 + 3] = f2tf32(v.w);
        }
        __syncthreads();

#pragma unroll
        for (int ks = 0; ks < 32; ks += 8) {
            unsigned bf[8][2];
#pragma unroll
            for (int nt = 0; nt < 8; nt++) {
                const int n = warpN * 64 + nt * 8 + gid;
                bf[nt][0] = __float_as_uint(Bs[ks + tig][n]);
                bf[nt][1] = __float_as_uint(Bs[ks + tig + 4][n]);
            }
#pragma unroll
            for (int mt = 0; mt < 2; mt++) {
                const int m = warpM * 32 + mt * 16;
                float2 lo = *(const float2*)&As[m + gid][ks + 2 * tig];
                float2 hi = *(const float2*)&As[m + gid + 8][ks + 2 * tig];
                const unsigned a0 = __float_as_uint(lo.x);
                const unsigned a1 = __float_as_uint(hi.x);
                const unsigned a2 = __float_as_uint(lo.y);
                const unsigned a3 = __float_as_uint(hi.y);
#pragma unroll
                for (int nt = 0; nt < 8; nt++)
                    mma_tf32(acc[mt][nt], a0, a1, a2, a3, bf[nt][0], bf[nt][1]);
            }
        }
        __syncthreads();
    }
}

// QKV projection: writes to g_q/g_k/g_v in [B,H,S,HD] layout. gridDim.z = 3.
__global__ void __launch_bounds__(256, 2)
qkv_proj_kernel(const float* __restrict__ x,
                const float* __restrict__ Wq, const float* __restrict__ bq,
                const float* __restrict__ Wk, const float* __restrict__ bk,
                const float* __restrict__ Wv, const float* __restrict__ bv) {
    const float* W;
    const float* bias;
    float* out;
    if (blockIdx.z == 0) { W = Wq; bias = bq; out = g_q; }
    else if (blockIdx.z == 1) { W = Wk; bias = bk; out = g_k; }
    else { W = Wv; bias = bv; out = g_v; }

    float acc[2][8][4] = {};
    sgemm_mma(x, W, acc);

    const int lane = threadIdx.x & 31;
    const int wid = threadIdx.x >> 5;
    const int warpM = wid >> 1, warpN = wid & 1;
    const int gid = lane >> 2, tig = lane & 3;
    const int mBase = blockIdx.y * 128, nBase = blockIdx.x * 128;

#pragma unroll
    for (int mt = 0; mt < 2; mt++) {
#pragma unroll
        for (int nt = 0; nt < 8; nt++) {
            const int c = nBase + warpN * 64 + nt * 8 + tig * 2;
            const int h = c >> 6, hd = c & 63;
            const float b0v = bias[c], b1v = bias[c + 1];
#pragma unroll
            for (int half = 0; half < 2; half++) {
                const int r = mBase + warpM * 32 + mt * 16 + gid + half * 8;
                const int b = r >> 11, s = r & 2047;
                float2 val;
                val.x = acc[mt][nt][half * 2 + 0] + b0v;
                val.y = acc[mt][nt][half * 2 + 1] + b1v;
                *(float2*)&out[(((b * NH + h) * NS + s) << 6) + hd] = val;
            }
        }
    }
}

// Output projection: out = g_ctx @ Wo + bo  (plain [M,N] layout)
__global__ void __launch_bounds__(256, 2)
out_proj_kernel(const float* __restrict__ Wo, const float* __restrict__ bo,
                float* __restrict__ out) {
    float acc[2][8][4] = {};
    sgemm_mma(g_ctx, Wo, acc);

    const int lane = threadIdx.x & 31;
    const int wid = threadIdx.x >> 5;
    const int warpM = wid >> 1, warpN = wid & 1;
    const int gid = lane >> 2, tig = lane & 3;
    const int mBase = blockIdx.y * 128, nBase = blockIdx.x * 128;

#pragma unroll
    for (int mt = 0; mt < 2; mt++) {
#pragma unroll
        for (int nt = 0; nt < 8; nt++) {
            const int c = nBase + warpN * 64 + nt * 8 + tig * 2;
            const float b0v = bo[c], b1v = bo[c + 1];
#pragma unroll
            for (int half = 0; half < 2; half++) {
                const int r = mBase + warpM * 32 + mt * 16 + gid + half * 8;
                float2 val;
                val.x = acc[mt][nt][half * 2 + 0] + b0v;
                val.y = acc[mt][nt][half * 2 + 1] + b1v;
                *(float2*)&out[(size_t)r * ND + c] = val;
            }
        }
    }
}

// ---------------------------------------------------------------------------
// FlashAttention-2, register-resident softmax. 128q-rows/CTA, 64-key tiles.
// 8 warps, each owns 16 query rows x all 64 keys. grid=(S/128, H, B).
// Smem: Qs[128][72] | Ks[64][72] | Vt[64][72] (V transposed, plain order).
// The S accumulator fragment is reused directly as the P a-fragment
// (reg order {c0,c2,c1,c3}); all b-frags are conflict-free LDS.64.
// ---------------------------------------------------------------------------
#define FSTR 72
#define FQ_OFF 0
#define FK_OFF (128 * FSTR)
#define FV_OFF (FK_OFF + 64 * FSTR)
#define F_SMEM_FLOATS (FV_OFF + 64 * FSTR)
#define F_SMEM_BYTES (F_SMEM_FLOATS * 4)

__global__ void __launch_bounds__(256, 2) flash_attn_kernel() {
    extern __shared__ float sm[];
    float* Qs = sm + FQ_OFF;
    float* Ks = sm + FK_OFF;
    float* Vt = sm + FV_OFF;

    const int tid = threadIdx.x;
    const int lane = tid & 31;
    const int wid = tid >> 5;        // 0..7, 16 query rows each
    const int gid = lane >> 2;       // 0..7
    const int tig = lane & 3;        // 0..3

    const int qt = gridDim.x - 1 - blockIdx.x;  // heavy tiles first
    const int h = blockIdx.y, b = blockIdx.z;
    const int bhBase = ((b * NH + h) * NS) << 6;
    const float* Qg = g_q + bhBase;
    const float* Kg = g_k + bhBase;
    const float* Vg = g_v + bhBase;

    // Load Q tile [128][64], scaled by 0.125, tf32-rounded
#pragma unroll
    for (int i = 0; i < 8; i++) {
        const int f4 = tid + i * 256;
        const int r = f4 >> 4, c4 = (f4 & 15) * 4;
        float4 v = *(const float4*)&Qg[((qt * 128 + r) << 6) + c4];
        float4 w;
        w.x = f2tf32(v.x * 0.125f);
        w.y = f2tf32(v.y * 0.125f);
        w.z = f2tf32(v.z * 0.125f);
        w.w = f2tf32(v.w * 0.125f);
        *(float4*)&Qs[r * FSTR + c4] = w;
    }

    float o[8][4] = {};
    float m0 = -1e30f, m1 = -1e30f, l0 = 0.0f, l1 = 0.0f;
    const int wBase = wid * 16;
    const int rowG0 = qt * 128 + wBase + gid;     // global row (low)
    const int ktMax = 2 * qt + 1;

    __syncthreads();

    for (int kt = 0; kt <= ktMax; kt++) {
        // ---- load K tile [64][64] plain ----
#pragma unroll
        for (int i = 0; i < 4; i++) {
            const int f4 = tid + i * 256;
            const int r = f4 >> 4, c4 = (f4 & 15) * 4;
            float4 v = *(const float4*)&Kg[((kt * 64 + r) << 6) + c4];
            float4 w;
            w.x = f2tf32(v.x); w.y = f2tf32(v.y);
            w.z = f2tf32(v.z); w.w = f2tf32(v.w);
            *(float4*)&Ks[r * FSTR + c4] = w;
        }
        // ---- load V tile transposed: Vt[hd][key] ----
        {
            const int r = tid & 63;            // key row
            const int c16 = (tid >> 6) * 16;   // hd chunk
#pragma unroll
            for (int k = 0; k < 4; k++) {
                float4 v = *(const float4*)&Vg[((kt * 64 + r) << 6) + c16 + k * 4];
                Vt[(c16 + k * 4 + 0) * FSTR + r] = f2tf32(v.x);
                Vt[(c16 + k * 4 + 1) * FSTR + r] = f2tf32(v.y);
                Vt[(c16 + k * 4 + 2) * FSTR + r] = f2tf32(v.z);
                Vt[(c16 + k * 4 + 3) * FSTR + r] = f2tf32(v.w);
            }
        }
        __syncthreads();

        // Warp-level skip: rows of this warp all above the key range -> masked out
        const bool active = (qt * 128 + wBase + 15) >= kt * 64;
        if (active) {
            // ---- S = Q @ K^T ----
            float s[8][4] = {};
#pragma unroll
            for (int kb = 0; kb < 8; kb++) {
                float2 qlo = *(const float2*)&Qs[(wBase + gid) * FSTR + kb * 8 + 2 * tig];
                float2 qhi = *(const float2*)&Qs[(wBase + gid + 8) * FSTR + kb * 8 + 2 * tig];
                const unsigned a0 = __float_as_uint(qlo.x);
                const unsigned a1 = __float_as_uint(qhi.x);
                const unsigned a2 = __float_as_uint(qlo.y);
                const unsigned a3 = __float_as_uint(qhi.y);
#pragma unroll
                for (int nt = 0; nt < 8; nt++) {
                    float2 bb = *(const float2*)&Ks[(nt * 8 + gid) * FSTR + kb * 8 + 2 * tig];
                    mma_tf32(s[nt], a0, a1, a2, a3,
                             __float_as_uint(bb.x), __float_as_uint(bb.y));
                }
            }

            // ---- causal mask (only the last two kt tiles need it) ----
            if (kt >= 2 * qt) {
#pragma unroll
                for (int nt = 0; nt < 8; nt++) {
                    const int col = kt * 64 + nt * 8 + 2 * tig;
                    if (col > rowG0) s[nt][0] = -1e30f;
                    if (col + 1 > rowG0) s[nt][1] = -1e30f;
                    if (col > rowG0 + 8) s[nt][2] = -1e30f;
                    if (col + 1 > rowG0 + 8) s[nt][3] = -1e30f;
                }
            }

            // ---- online softmax (registers + quad shuffles) ----
            float mx0 = -1e30f, mx1 = -1e30f;
#pragma unroll
            for (int nt = 0; nt < 8; nt++) {
                mx0 = fmaxf(mx0, fmaxf(s[nt][0], s[nt][1]));
                mx1 = fmaxf(mx1, fmaxf(s[nt][2], s[nt][3]));
            }
            mx0 = fmaxf(mx0, __shfl_xor_sync(0xffffffffu, mx0, 1));
            mx0 = fmaxf(mx0, __shfl_xor_sync(0xffffffffu, mx0, 2));
            mx1 = fmaxf(mx1, __shfl_xor_sync(0xffffffffu, mx1, 1));
            mx1 = fmaxf(mx1, __shfl_xor_sync(0xffffffffu, mx1, 2));
            const float mn0 = fmaxf(m0, mx0);
            const float mn1 = fmaxf(m1, mx1);
            const float al0 = __expf(m0 - mn0);
            const float al1 = __expf(m1 - mn1);
            m0 = mn0; m1 = mn1;
            float sum0 = 0.0f, sum1 = 0.0f;
#pragma unroll
            for (int nt = 0; nt < 8; nt++) {
                float p0 = __expf(s[nt][0] - mn0);
                float p1 = __expf(s[nt][1] - mn0);
                float p2 = __expf(s[nt][2] - mn1);
                float p3 = __expf(s[nt][3] - mn1);
                sum0 += p0 + p1;
                sum1 += p2 + p3;
                s[nt][0] = f2tf32(p0);
                s[nt][1] = f2tf32(p1);
                s[nt][2] = f2tf32(p2);
                s[nt][3] = f2tf32(p3);
            }
            sum0 += __shfl_xor_sync(0xffffffffu, sum0, 1);
            sum0 += __shfl_xor_sync(0xffffffffu, sum0, 2);
            sum1 += __shfl_xor_sync(0xffffffffu, sum1, 1);
            sum1 += __shfl_xor_sync(0xffffffffu, sum1, 2);
            l0 = l0 * al0 + sum0;
            l1 = l1 * al1 + sum1;

            // ---- O = O*alpha + P @ V (P frag reused from S regs) ----
#pragma unroll
            for (int nt = 0; nt < 8; nt++) {
                o[nt][0] *= al0; o[nt][1] *= al0;
                o[nt][2] *= al1; o[nt][3] *= al1;
            }
#pragma unroll
            for (int kb = 0; kb < 8; kb++) {
                const unsigned a0 = __float_as_uint(s[kb][0]);
                const unsigned a1 = __float_as_uint(s[kb][2]);
                const unsigned a2 = __float_as_uint(s[kb][1]);
                const unsigned a3 = __float_as_uint(s[kb][3]);
#pragma unroll
                for (int nt = 0; nt < 8; nt++) {
                    float2 bb = *(const float2*)&Vt[(nt * 8 + gid) * FSTR + kb * 8 + 2 * tig];
                    mma_tf32(o[nt], a0, a1, a2, a3,
                             __float_as_uint(bb.x), __float_as_uint(bb.y));
                }
            }
        }
        __syncthreads();
    }

    // ---- normalize and store ctx in [B,S,D] layout ----
    const float i0 = 1.0f / l0;
    const float i1 = 1.0f / l1;
    const int colBase = (h << 6) + 2 * tig;
#pragma unroll
    for (int nt = 0; nt < 8; nt++) {
        {
            float2 val = {o[nt][0] * i0, o[nt][1] * i0};
            *(float2*)&g_ctx[(size_t)(b * NS + rowG0) * ND + colBase + nt * 8] = val;
        }
        {
            float2 val = {o[nt][2] * i1, o[nt][3] * i1};
            *(float2*)&g_ctx[(size_t)(b * NS + rowG0 + 8) * ND + colBase + nt * 8] = val;
        }
    }
}

extern "C" void kernel_launch(void* const* d_in, const int* in_sizes, int n_in,
                              void* d_out, int out_size) {
    const float* x = (const float*)d_in[0];
    const float* Wq = (const float*)d_in[1];
    const float* bq = (const float*)d_in[2];
    const float* Wk = (const float*)d_in[3];
    const float* bk = (const float*)d_in[4];
    const float* Wv = (const float*)d_in[5];
    const float* bv = (const float*)d_in[6];
    const float* Wo = (const float*)d_in[7];
    const float* bo = (const float*)d_in[8];
    float* out = (float*)d_out;

    cudaFuncSetAttribute(flash_attn_kernel,
                         cudaFuncAttributeMaxDynamicSharedMemorySize,
                         F_SMEM_BYTES);

    dim3 g1(ND / 128, MTOT / 128, 3);
    qkv_proj_kernel<<<g1, 256>>>(x, Wq, bq, Wk, bk, Wv, bv);

    dim3 g2(NS / 128, NH, NB);
    flash_attn_kernel<<<g2, 256, F_SMEM_BYTES>>>();

    dim3 g3(ND / 128, MTOT / 128);
    out_proj_kernel<<<g3, 256>>>(Wo, bo, out);
}

// round 5
// speedup vs baseline: 3.4138x; 1.1206x over previous
#include <cuda_runtime.h>
#include <math.h>

#define NB 2
#define NS 2048
#define ND 1024
#define NH 16
#define NHD 64
#define MTOT (NB * NS)   // 4096

// Scratch (allocation-free rule: __device__ globals)
__device__ float g_q[NB * NH * NS * NHD];
__device__ float g_k[NB * NH * NS * NHD];
__device__ float g_v[NB * NH * NS * NHD];
__device__ float g_ctx[NB * NS * ND];      // tf32-rounded, permk'd columns
__device__ float g_xr[MTOT * ND];          // x, tf32-rounded, permk'd columns
__device__ float g_wr[4][ND * ND];         // W^T, tf32-rounded, permk'd columns

// ---------------------------------------------------------------------------
// helpers
// ---------------------------------------------------------------------------
__device__ __forceinline__ float f2tf32(float x) {
    unsigned r;
    asm("cvt.rna.tf32.f32 %0, %1;" : "=r"(r) : "f"(x));
    return __uint_as_float(r);
}

__device__ __forceinline__ void mma_tf32(float (&c)[4], unsigned a0, unsigned a1,
                                         unsigned a2, unsigned a3, unsigned b0,
                                         unsigned b1) {
    asm volatile(
        "mma.sync.aligned.m16n8k8.row.col.f32.tf32.tf32.f32 "
        "{%0,%1,%2,%3}, {%4,%5,%6,%7}, {%8,%9}, {%0,%1,%2,%3};\n"
        : "+f"(c[0]), "+f"(c[1]), "+f"(c[2]), "+f"(c[3])
        : "r"(a0), "r"(a1), "r"(a2), "r"(a3), "r"(b0), "r"(b1));
}

// interleave k within 8-blocks so fragment pairs (k, k+4) are adjacent.
// Works on globally flattened indices too (row strides are multiples of 8).
__device__ __forceinline__ int permk(int c) {
    return (c & ~7) | ((c & 3) << 1) | ((c >> 2) & 1);
}

// ---------------------------------------------------------------------------
// Prep kernels: tf32-round + permute (x) / transpose+round+permute (W)
// ---------------------------------------------------------------------------
__global__ void __launch_bounds__(256)
round_x_kernel(const float* __restrict__ x) {
    const int f4 = blockIdx.x * 256 + threadIdx.x;   // over 1M float4s
    const int base = f4 * 4;
    float4 v = *(const float4*)&x[base];
    g_xr[permk(base + 0)] = f2tf32(v.x);
    g_xr[permk(base + 1)] = f2tf32(v.y);
    g_xr[permk(base + 2)] = f2tf32(v.z);
    g_xr[permk(base + 3)] = f2tf32(v.w);
}

// g_wr[w][n*ND + permk(k)] = tf32(W[k*ND + n]); block = 32x8, tile 32x32
__global__ void __launch_bounds__(256)
round_w_kernel(const float* __restrict__ Wq, const float* __restrict__ Wk,
               const float* __restrict__ Wv, const float* __restrict__ Wo) {
    __shared__ float t[32][33];
    const float* W;
    if (blockIdx.z == 0) W = Wq;
    else if (blockIdx.z == 1) W = Wk;
    else if (blockIdx.z == 2) W = Wv;
    else W = Wo;
    float* out = &g_wr[blockIdx.z][0];

    const int k0 = blockIdx.x * 32, n0 = blockIdx.y * 32;
    const int tx = threadIdx.x, ty = threadIdx.y;
#pragma unroll
    for (int i = 0; i < 4; i++)
        t[ty + i * 8][tx] = W[(size_t)(k0 + ty + i * 8) * ND + n0 + tx];
    __syncthreads();
#pragma unroll
    for (int i = 0; i < 4; i++)
        out[(size_t)(n0 + ty + i * 8) * ND + k0 + permk(tx)] =
            f2tf32(t[tx][ty + i * 8]);
}

// ---------------------------------------------------------------------------
// 128x128x32 TF32 tensor-core GEMM tile: C = A[128x1024] @ Bt[128x1024]^T
// A and Bt are pre-rounded, pre-permuted (fragment pairs adjacent).
// 256 threads, 8 warps in 4(M) x 2(N); warp tile 32x64 = 2x8 m16n8k8 atoms.
// Smem stride 40 -> LDS.64 bank pattern (8g+2t) is conflict-free.
// ---------------------------------------------------------------------------
__device__ __forceinline__ void sgemm_mma(const float* __restrict__ A,
                                          const float* __restrict__ Bt,
                                          float (&acc)[2][8][4]) {
    __shared__ float As[128][40];
    __shared__ float Bs[128][40];

    const int tid = threadIdx.x;
    const int lane = tid & 31;
    const int wid = tid >> 5;
    const int warpM = wid >> 1;   // 0..3
    const int warpN = wid & 1;    // 0..1
    const int gid = lane >> 2;    // 0..7
    const int tig = lane & 3;     // 0..3
    const int mBase = blockIdx.y * 128;
    const int nBase = blockIdx.x * 128;

    for (int k0 = 0; k0 < ND; k0 += 32) {
#pragma unroll
        for (int i = 0; i < 4; i++) {
            const int f4 = tid + i * 256;
            const int m = f4 >> 3, c4 = (f4 & 7) * 4;
            *(float4*)&As[m][c4] =
                *(const float4*)&A[(size_t)(mBase + m) * ND + k0 + c4];
            *(float4*)&Bs[m][c4] =
                *(const float4*)&Bt[(size_t)(nBase + m) * ND + k0 + c4];
        }
        __syncthreads();

#pragma unroll
        for (int ks = 0; ks < 32; ks += 8) {
            unsigned bf[8][2];
#pragma unroll
            for (int nt = 0; nt < 8; nt++) {
                float2 bb = *(const float2*)&Bs[warpN * 64 + nt * 8 + gid][ks + 2 * tig];
                bf[nt][0] = __float_as_uint(bb.x);
                bf[nt][1] = __float_as_uint(bb.y);
            }
#pragma unroll
            for (int mt = 0; mt < 2; mt++) {
                const int m = warpM * 32 + mt * 16;
                float2 lo = *(const float2*)&As[m + gid][ks + 2 * tig];
                float2 hi = *(const float2*)&As[m + gid + 8][ks + 2 * tig];
                const unsigned a0 = __float_as_uint(lo.x);
                const unsigned a1 = __float_as_uint(hi.x);
                const unsigned a2 = __float_as_uint(lo.y);
                const unsigned a3 = __float_as_uint(hi.y);
#pragma unroll
                for (int nt = 0; nt < 8; nt++)
                    mma_tf32(acc[mt][nt], a0, a1, a2, a3, bf[nt][0], bf[nt][1]);
            }
        }
        __syncthreads();
    }
}

// QKV projection: writes tf32-rounded Q(pre-scaled)/K/V in [B,H,S,HD]. z=3.
__global__ void __launch_bounds__(256, 2)
qkv_proj_kernel(const float* __restrict__ bq, const float* __restrict__ bk,
                const float* __restrict__ bv) {
    const float* Bt;
    const float* bias;
    float* out;
    float sc;
    if (blockIdx.z == 0) { Bt = g_wr[0]; bias = bq; out = g_q; sc = 0.125f; }
    else if (blockIdx.z == 1) { Bt = g_wr[1]; bias = bk; out = g_k; sc = 1.0f; }
    else { Bt = g_wr[2]; bias = bv; out = g_v; sc = 1.0f; }

    float acc[2][8][4] = {};
    sgemm_mma(g_xr, Bt, acc);

    const int lane = threadIdx.x & 31;
    const int wid = threadIdx.x >> 5;
    const int warpM = wid >> 1, warpN = wid & 1;
    const int gid = lane >> 2, tig = lane & 3;
    const int mBase = blockIdx.y * 128, nBase = blockIdx.x * 128;

#pragma unroll
    for (int mt = 0; mt < 2; mt++) {
#pragma unroll
        for (int nt = 0; nt < 8; nt++) {
            const int c = nBase + warpN * 64 + nt * 8 + tig * 2;
            const int h = c >> 6, hd = c & 63;
            const float b0v = bias[c], b1v = bias[c + 1];
#pragma unroll
            for (int half = 0; half < 2; half++) {
                const int r = mBase + warpM * 32 + mt * 16 + gid + half * 8;
                const int b = r >> 11, s = r & 2047;
                float2 val;
                val.x = f2tf32((acc[mt][nt][half * 2 + 0] + b0v) * sc);
                val.y = f2tf32((acc[mt][nt][half * 2 + 1] + b1v) * sc);
                *(float2*)&out[(((b * NH + h) * NS + s) << 6) + hd] = val;
            }
        }
    }
}

// Output projection: out = ctx @ Wo + bo (ctx pre-rounded/permuted by flash)
__global__ void __launch_bounds__(256, 2)
out_proj_kernel(const float* __restrict__ bo, float* __restrict__ out) {
    float acc[2][8][4] = {};
    sgemm_mma(g_ctx, g_wr[3], acc);

    const int lane = threadIdx.x & 31;
    const int wid = threadIdx.x >> 5;
    const int warpM = wid >> 1, warpN = wid & 1;
    const int gid = lane >> 2, tig = lane & 3;
    const int mBase = blockIdx.y * 128, nBase = blockIdx.x * 128;

#pragma unroll
    for (int mt = 0; mt < 2; mt++) {
#pragma unroll
        for (int nt = 0; nt < 8; nt++) {
            const int c = nBase + warpN * 64 + nt * 8 + tig * 2;
            const float b0v = bo[c], b1v = bo[c + 1];
#pragma unroll
            for (int half = 0; half < 2; half++) {
                const int r = mBase + warpM * 32 + mt * 16 + gid + half * 8;
                float2 val;
                val.x = acc[mt][nt][half * 2 + 0] + b0v;
                val.y = acc[mt][nt][half * 2 + 1] + b1v;
                *(float2*)&out[(size_t)r * ND + c] = val;
            }
        }
    }
}

// ---------------------------------------------------------------------------
// FlashAttention-2, register-resident softmax. 128q-rows/CTA, 64-key tiles.
// Inputs are pre-rounded (Q pre-scaled), so all loads are raw copies.
// Output ctx is stored tf32-rounded with permk'd columns for out_proj.
// ---------------------------------------------------------------------------
#define FSTR 72
#define FQ_OFF 0
#define FK_OFF (128 * FSTR)
#define FV_OFF (FK_OFF + 64 * FSTR)
#define F_SMEM_FLOATS (FV_OFF + 64 * FSTR)
#define F_SMEM_BYTES (F_SMEM_FLOATS * 4)

__global__ void __launch_bounds__(256, 2) flash_attn_kernel() {
    extern __shared__ float sm[];
    float* Qs = sm + FQ_OFF;
    float* Ks = sm + FK_OFF;
    float* Vt = sm + FV_OFF;

    const int tid = threadIdx.x;
    const int lane = tid & 31;
    const int wid = tid >> 5;        // 0..7, 16 query rows each
    const int gid = lane >> 2;       // 0..7
    const int tig = lane & 3;        // 0..3

    const int qt = gridDim.x - 1 - blockIdx.x;  // heavy tiles first
    const int h = blockIdx.y, b = blockIdx.z;
    const int bhBase = ((b * NH + h) * NS) << 6;
    const float* Qg = g_q + bhBase;
    const float* Kg = g_k + bhBase;
    const float* Vg = g_v + bhBase;

    // Load Q tile [128][64] (already rounded + scaled)
#pragma unroll
    for (int i = 0; i < 8; i++) {
        const int f4 = tid + i * 256;
        const int r = f4 >> 4, c4 = (f4 & 15) * 4;
        *(float4*)&Qs[r * FSTR + c4] =
            *(const float4*)&Qg[((qt * 128 + r) << 6) + c4];
    }

    float o[8][4] = {};
    float m0 = -1e30f, m1 = -1e30f, l0 = 0.0f, l1 = 0.0f;
    const int wBase = wid * 16;
    const int rowG0 = qt * 128 + wBase + gid;     // global row (low)
    const int ktMax = 2 * qt + 1;

    __syncthreads();

    for (int kt = 0; kt <= ktMax; kt++) {
        // ---- load K tile [64][64] plain ----
#pragma unroll
        for (int i = 0; i < 4; i++) {
            const int f4 = tid + i * 256;
            const int r = f4 >> 4, c4 = (f4 & 15) * 4;
            *(float4*)&Ks[r * FSTR + c4] =
                *(const float4*)&Kg[((kt * 64 + r) << 6) + c4];
        }
        // ---- load V tile transposed: Vt[hd][key] ----
        {
            const int r = tid & 63;            // key row
            const int c16 = (tid >> 6) * 16;   // hd chunk
#pragma unroll
            for (int k = 0; k < 4; k++) {
                float4 v = *(const float4*)&Vg[((kt * 64 + r) << 6) + c16 + k * 4];
                Vt[(c16 + k * 4 + 0) * FSTR + r] = v.x;
                Vt[(c16 + k * 4 + 1) * FSTR + r] = v.y;
                Vt[(c16 + k * 4 + 2) * FSTR + r] = v.z;
                Vt[(c16 + k * 4 + 3) * FSTR + r] = v.w;
            }
        }
        __syncthreads();

        // Warp-level skip: rows of this warp all above the key range -> masked
        const bool active = (qt * 128 + wBase + 15) >= kt * 64;
        if (active) {
            // ---- S = Q @ K^T ----
            float s[8][4] = {};
#pragma unroll
            for (int kb = 0; kb < 8; kb++) {
                float2 qlo = *(const float2*)&Qs[(wBase + gid) * FSTR + kb * 8 + 2 * tig];
                float2 qhi = *(const float2*)&Qs[(wBase + gid + 8) * FSTR + kb * 8 + 2 * tig];
                const unsigned a0 = __float_as_uint(qlo.x);
                const unsigned a1 = __float_as_uint(qhi.x);
                const unsigned a2 = __float_as_uint(qlo.y);
                const unsigned a3 = __float_as_uint(qhi.y);
#pragma unroll
                for (int nt = 0; nt < 8; nt++) {
                    float2 bb = *(const float2*)&Ks[(nt * 8 + gid) * FSTR + kb * 8 + 2 * tig];
                    mma_tf32(s[nt], a0, a1, a2, a3,
                             __float_as_uint(bb.x), __float_as_uint(bb.y));
                }
            }

            // ---- causal mask (only the last two kt tiles need it) ----
            if (kt >= 2 * qt) {
#pragma unroll
                for (int nt = 0; nt < 8; nt++) {
                    const int col = kt * 64 + nt * 8 + 2 * tig;
                    if (col > rowG0) s[nt][0] = -1e30f;
                    if (col + 1 > rowG0) s[nt][1] = -1e30f;
                    if (col > rowG0 + 8) s[nt][2] = -1e30f;
                    if (col + 1 > rowG0 + 8) s[nt][3] = -1e30f;
                }
            }

            // ---- online softmax (registers + quad shuffles) ----
            float mx0 = -1e30f, mx1 = -1e30f;
#pragma unroll
            for (int nt = 0; nt < 8; nt++) {
                mx0 = fmaxf(mx0, fmaxf(s[nt][0], s[nt][1]));
                mx1 = fmaxf(mx1, fmaxf(s[nt][2], s[nt][3]));
            }
            mx0 = fmaxf(mx0, __shfl_xor_sync(0xffffffffu, mx0, 1));
            mx0 = fmaxf(mx0, __shfl_xor_sync(0xffffffffu, mx0, 2));
            mx1 = fmaxf(mx1, __shfl_xor_sync(0xffffffffu, mx1, 1));
            mx1 = fmaxf(mx1, __shfl_xor_sync(0xffffffffu, mx1, 2));
            const float mn0 = fmaxf(m0, mx0);
            const float mn1 = fmaxf(m1, mx1);
            const float al0 = __expf(m0 - mn0);
            const float al1 = __expf(m1 - mn1);
            m0 = mn0; m1 = mn1;
            float sum0 = 0.0f, sum1 = 0.0f;
#pragma unroll
            for (int nt = 0; nt < 8; nt++) {
                float p0 = __expf(s[nt][0] - mn0);
                float p1 = __expf(s[nt][1] - mn0);
                float p2 = __expf(s[nt][2] - mn1);
                float p3 = __expf(s[nt][3] - mn1);
                sum0 += p0 + p1;
                sum1 += p2 + p3;
                s[nt][0] = f2tf32(p0);
                s[nt][1] = f2tf32(p1);
                s[nt][2] = f2tf32(p2);
                s[nt][3] = f2tf32(p3);
            }
            sum0 += __shfl_xor_sync(0xffffffffu, sum0, 1);
            sum0 += __shfl_xor_sync(0xffffffffu, sum0, 2);
            sum1 += __shfl_xor_sync(0xffffffffu, sum1, 1);
            sum1 += __shfl_xor_sync(0xffffffffu, sum1, 2);
            l0 = l0 * al0 + sum0;
            l1 = l1 * al1 + sum1;

            // ---- O = O*alpha + P @ V (P frag reused from S regs) ----
#pragma unroll
            for (int nt = 0; nt < 8; nt++) {
                o[nt][0] *= al0; o[nt][1] *= al0;
                o[nt][2] *= al1; o[nt][3] *= al1;
            }
#pragma unroll
            for (int kb = 0; kb < 8; kb++) {
                const unsigned a0 = __float_as_uint(s[kb][0]);
                const unsigned a1 = __float_as_uint(s[kb][2]);
                const unsigned a2 = __float_as_uint(s[kb][1]);
                const unsigned a3 = __float_as_uint(s[kb][3]);
#pragma unroll
                for (int nt = 0; nt < 8; nt++) {
                    float2 bb = *(const float2*)&Vt[(nt * 8 + gid) * FSTR + kb * 8 + 2 * tig];
                    mma_tf32(o[nt], a0, a1, a2, a3,
                             __float_as_uint(bb.x), __float_as_uint(bb.y));
                }
            }
        }
        __syncthreads();
    }

    // ---- normalize, round, store ctx permk'd in [B,S,D] for out_proj ----
    const float i0 = 1.0f / l0;
    const float i1 = 1.0f / l1;
    const int colBase = (h << 6) + 2 * tig;
    float* row0 = &g_ctx[(size_t)(b * NS + rowG0) * ND];
    float* row1 = &g_ctx[(size_t)(b * NS + rowG0 + 8) * ND];
#pragma unroll
    for (int nt = 0; nt < 8; nt++) {
        const int c = colBase + nt * 8;
        row0[permk(c)] = f2tf32(o[nt][0] * i0);
        row0[permk(c + 1)] = f2tf32(o[nt][1] * i0);
        row1[permk(c)] = f2tf32(o[nt][2] * i1);
        row1[permk(c + 1)] = f2tf32(o[nt][3] * i1);
    }
}

extern "C" void kernel_launch(void* const* d_in, const int* in_sizes, int n_in,
                              void* d_out, int out_size) {
    const float* x = (const float*)d_in[0];
    const float* Wq = (const float*)d_in[1];
    const float* bq = (const float*)d_in[2];
    const float* Wk = (const float*)d_in[3];
    const float* bk = (const float*)d_in[4];
    const float* Wv = (const float*)d_in[5];
    const float* bv = (const float*)d_in[6];
    const float* Wo = (const float*)d_in[7];
    const float* bo = (const float*)d_in[8];
    float* out = (float*)d_out;

    cudaFuncSetAttribute(flash_attn_kernel,
                         cudaFuncAttributeMaxDynamicSharedMemorySize,
                         F_SMEM_BYTES);

    // Prep: round + permute x; transpose + round + permute all W
    round_x_kernel<<<MTOT * ND / 1024, 256>>>(x);
    dim3 gw(ND / 32, ND / 32, 4);
    round_w_kernel<<<gw, dim3(32, 8)>>>(Wq, Wk, Wv, Wo);

    dim3 g1(ND / 128, MTOT / 128, 3);
    qkv_proj_kernel<<<g1, 256>>>(bq, bk, bv);

    dim3 g2(NS / 128, NH, NB);
    flash_attn_kernel<<<g2, 256, F_SMEM_BYTES>>>();

    dim3 g3(ND / 128, MTOT / 128);
    out_proj_kernel<<<g3, 256>>>(bo, out);
}

// round 6
// speedup vs baseline: 3.8650x; 1.1322x over previous
#include <cuda_runtime.h>
#include <math.h>

#define NB 2
#define NS 2048
#define ND 1024
#define NH 16
#define NHD 64
#define MTOT (NB * NS)   // 4096

// Scratch (allocation-free rule: __device__ globals)
__device__ float g_q[NB * NH * NS * NHD];
__device__ float g_k[NB * NH * NS * NHD];
__device__ float g_v[NB * NH * NS * NHD];
__device__ float g_ctx[NB * NS * ND];      // tf32-rounded, permk'd columns
__device__ float g_xr[MTOT * ND];          // x, tf32-rounded, permk'd columns
__device__ float g_wr[4][ND * ND];         // W^T, tf32-rounded, permk'd columns

// ---------------------------------------------------------------------------
// helpers
// ---------------------------------------------------------------------------
__device__ __forceinline__ float f2tf32(float x) {
    unsigned r;
    asm("cvt.rna.tf32.f32 %0, %1;" : "=r"(r) : "f"(x));
    return __uint_as_float(r);
}

__device__ __forceinline__ void mma_tf32(float (&c)[4], unsigned a0, unsigned a1,
                                         unsigned a2, unsigned a3, unsigned b0,
                                         unsigned b1) {
    asm volatile(
        "mma.sync.aligned.m16n8k8.row.col.f32.tf32.tf32.f32 "
        "{%0,%1,%2,%3}, {%4,%5,%6,%7}, {%8,%9}, {%0,%1,%2,%3};\n"
        : "+f"(c[0]), "+f"(c[1]), "+f"(c[2]), "+f"(c[3])
        : "r"(a0), "r"(a1), "r"(a2), "r"(a3), "r"(b0), "r"(b1));
}

__device__ __forceinline__ unsigned smaddr(const void* p) {
    return (unsigned)__cvta_generic_to_shared(p);
}
#define CP_ASYNC16(dst, src) \
    asm volatile("cp.async.cg.shared.global [%0], [%1], 16;\n" ::"r"(dst), "l"(src))
#define CP_COMMIT() asm volatile("cp.async.commit_group;\n")
#define CP_WAIT(n) asm volatile("cp.async.wait_group %0;\n" ::"n"(n))

// interleave k within 8-blocks so fragment pairs (k, k+4) are adjacent.
__device__ __forceinline__ int permk(int c) {
    return (c & ~7) | ((c & 3) << 1) | ((c >> 2) & 1);
}

// ---------------------------------------------------------------------------
// Prep kernels: tf32-round + permute (x) / transpose+round+permute (W)
// ---------------------------------------------------------------------------
__global__ void __launch_bounds__(256)
round_x_kernel(const float* __restrict__ x) {
    const int f4 = blockIdx.x * 256 + threadIdx.x;
    const int base = f4 * 4;
    float4 v = *(const float4*)&x[base];
    g_xr[permk(base + 0)] = f2tf32(v.x);
    g_xr[permk(base + 1)] = f2tf32(v.y);
    g_xr[permk(base + 2)] = f2tf32(v.z);
    g_xr[permk(base + 3)] = f2tf32(v.w);
}

__global__ void __launch_bounds__(256)
round_w_kernel(const float* __restrict__ Wq, const float* __restrict__ Wk,
               const float* __restrict__ Wv, const float* __restrict__ Wo) {
    __shared__ float t[32][33];
    const float* W;
    if (blockIdx.z == 0) W = Wq;
    else if (blockIdx.z == 1) W = Wk;
    else if (blockIdx.z == 2) W = Wv;
    else W = Wo;
    float* out = &g_wr[blockIdx.z][0];

    const int k0 = blockIdx.x * 32, n0 = blockIdx.y * 32;
    const int tx = threadIdx.x, ty = threadIdx.y;
#pragma unroll
    for (int i = 0; i < 4; i++)
        t[ty + i * 8][tx] = W[(size_t)(k0 + ty + i * 8) * ND + n0 + tx];
    __syncthreads();
#pragma unroll
    for (int i = 0; i < 4; i++)
        out[(size_t)(n0 + ty + i * 8) * ND + k0 + permk(tx)] =
            f2tf32(t[tx][ty + i * 8]);
}

// ---------------------------------------------------------------------------
// 128x128x32 TF32 GEMM tile, 2-stage cp.async pipeline.
// Dynamic smem: As[2][128][40] | Bs[2][128][40]  (80 KB)
// ---------------------------------------------------------------------------
#define GEMM_STG (128 * 40)
#define GEMM_SMEM_FLOATS (4 * GEMM_STG)
#define GEMM_SMEM_BYTES (GEMM_SMEM_FLOATS * 4)

__device__ __forceinline__ void sgemm_mma(const float* __restrict__ A,
                                          const float* __restrict__ Bt,
                                          float (&acc)[2][8][4]) {
    extern __shared__ float gsm[];
    float* AsBase = gsm;                 // 2 stages of 128x40
    float* BsBase = gsm + 2 * GEMM_STG;  // 2 stages of 128x40

    const int tid = threadIdx.x;
    const int lane = tid & 31;
    const int wid = tid >> 5;
    const int warpM = wid >> 1;
    const int warpN = wid & 1;
    const int gid = lane >> 2;
    const int tig = lane & 3;
    const int mBase = blockIdx.y * 128;
    const int nBase = blockIdx.x * 128;

    // prologue: stage 0
#pragma unroll
    for (int i = 0; i < 4; i++) {
        const int f4 = tid + i * 256;
        const int m = f4 >> 3, c4 = (f4 & 7) * 4;
        CP_ASYNC16(smaddr(&AsBase[m * 40 + c4]),
                   &A[(size_t)(mBase + m) * ND + c4]);
        CP_ASYNC16(smaddr(&BsBase[m * 40 + c4]),
                   &Bt[(size_t)(nBase + m) * ND + c4]);
    }
    CP_COMMIT();

    for (int k0 = 0; k0 < ND; k0 += 32) {
        const int st = (k0 >> 5) & 1;
        if (k0 + 32 < ND) {
            float* An = AsBase + (st ^ 1) * GEMM_STG;
            float* Bn = BsBase + (st ^ 1) * GEMM_STG;
#pragma unroll
            for (int i = 0; i < 4; i++) {
                const int f4 = tid + i * 256;
                const int m = f4 >> 3, c4 = (f4 & 7) * 4;
                CP_ASYNC16(smaddr(&An[m * 40 + c4]),
                           &A[(size_t)(mBase + m) * ND + k0 + 32 + c4]);
                CP_ASYNC16(smaddr(&Bn[m * 40 + c4]),
                           &Bt[(size_t)(nBase + m) * ND + k0 + 32 + c4]);
            }
            CP_COMMIT();
            CP_WAIT(1);
        } else {
            CP_WAIT(0);
        }
        __syncthreads();

        const float* As = AsBase + st * GEMM_STG;
        const float* Bs = BsBase + st * GEMM_STG;
#pragma unroll
        for (int ks = 0; ks < 32; ks += 8) {
            unsigned bf[8][2];
#pragma unroll
            for (int nt = 0; nt < 8; nt++) {
                float2 bb = *(const float2*)&Bs[(warpN * 64 + nt * 8 + gid) * 40 + ks + 2 * tig];
                bf[nt][0] = __float_as_uint(bb.x);
                bf[nt][1] = __float_as_uint(bb.y);
            }
#pragma unroll
            for (int mt = 0; mt < 2; mt++) {
                const int m = warpM * 32 + mt * 16;
                float2 lo = *(const float2*)&As[(m + gid) * 40 + ks + 2 * tig];
                float2 hi = *(const float2*)&As[(m + gid + 8) * 40 + ks + 2 * tig];
                const unsigned a0 = __float_as_uint(lo.x);
                const unsigned a1 = __float_as_uint(hi.x);
                const unsigned a2 = __float_as_uint(lo.y);
                const unsigned a3 = __float_as_uint(hi.y);
#pragma unroll
                for (int nt = 0; nt < 8; nt++)
                    mma_tf32(acc[mt][nt], a0, a1, a2, a3, bf[nt][0], bf[nt][1]);
            }
        }
        __syncthreads();
    }
}

// QKV projection: writes tf32-rounded Q(pre-scaled)/K/V in [B,H,S,HD]. z=3.
__global__ void __launch_bounds__(256, 2)
qkv_proj_kernel(const float* __restrict__ bq, const float* __restrict__ bk,
                const float* __restrict__ bv) {
    const float* Bt;
    const float* bias;
    float* out;
    float sc;
    if (blockIdx.z == 0) { Bt = g_wr[0]; bias = bq; out = g_q; sc = 0.125f; }
    else if (blockIdx.z == 1) { Bt = g_wr[1]; bias = bk; out = g_k; sc = 1.0f; }
    else { Bt = g_wr[2]; bias = bv; out = g_v; sc = 1.0f; }

    float acc[2][8][4] = {};
    sgemm_mma(g_xr, Bt, acc);

    const int lane = threadIdx.x & 31;
    const int wid = threadIdx.x >> 5;
    const int warpM = wid >> 1, warpN = wid & 1;
    const int gid = lane >> 2, tig = lane & 3;
    const int mBase = blockIdx.y * 128, nBase = blockIdx.x * 128;

#pragma unroll
    for (int mt = 0; mt < 2; mt++) {
#pragma unroll
        for (int nt = 0; nt < 8; nt++) {
            const int c = nBase + warpN * 64 + nt * 8 + tig * 2;
            const int h = c >> 6, hd = c & 63;
            const float b0v = bias[c], b1v = bias[c + 1];
#pragma unroll
            for (int half = 0; half < 2; half++) {
                const int r = mBase + warpM * 32 + mt * 16 + gid + half * 8;
                const int b = r >> 11, s = r & 2047;
                float2 val;
                val.x = f2tf32((acc[mt][nt][half * 2 + 0] + b0v) * sc);
                val.y = f2tf32((acc[mt][nt][half * 2 + 1] + b1v) * sc);
                *(float2*)&out[(((b * NH + h) * NS + s) << 6) + hd] = val;
            }
        }
    }
}

// Output projection: out = ctx @ Wo + bo (ctx pre-rounded/permuted by flash)
__global__ void __launch_bounds__(256, 2)
out_proj_kernel(const float* __restrict__ bo, float* __restrict__ out) {
    float acc[2][8][4] = {};
    sgemm_mma(g_ctx, g_wr[3], acc);

    const int lane = threadIdx.x & 31;
    const int wid = threadIdx.x >> 5;
    const int warpM = wid >> 1, warpN = wid & 1;
    const int gid = lane >> 2, tig = lane & 3;
    const int mBase = blockIdx.y * 128, nBase = blockIdx.x * 128;

#pragma unroll
    for (int mt = 0; mt < 2; mt++) {
#pragma unroll
        for (int nt = 0; nt < 8; nt++) {
            const int c = nBase + warpN * 64 + nt * 8 + tig * 2;
            const float b0v = bo[c], b1v = bo[c + 1];
#pragma unroll
            for (int half = 0; half < 2; half++) {
                const int r = mBase + warpM * 32 + mt * 16 + gid + half * 8;
                float2 val;
                val.x = acc[mt][nt][half * 2 + 0] + b0v;
                val.y = acc[mt][nt][half * 2 + 1] + b1v;
                *(float2*)&out[(size_t)r * ND + c] = val;
            }
        }
    }
}

// ---------------------------------------------------------------------------
// FlashAttention-2, cp.async double-buffered K/V, register softmax.
// 128q/CTA, 64-key tiles. Q stride 72, K stride 72, V plain [key][hd] str 76.
// PV b-frags = scalar pair loads from plain V (stride 76 -> conflict-free).
// Smem floats: Q 128*72 | K[2] 64*72 | V[2] 64*76   = 28160 (112.6 KB)
// ---------------------------------------------------------------------------
#define FQS 72
#define FVS 76
#define FQ_OFF 0
#define FK_OFF (128 * FQS)
#define FV_OFF (FK_OFF + 2 * 64 * FQS)
#define F_SMEM_FLOATS (FV_OFF + 2 * 64 * FVS)
#define F_SMEM_BYTES (F_SMEM_FLOATS * 4)

__global__ void __launch_bounds__(256, 2) flash_attn_kernel() {
    extern __shared__ float sm[];
    float* Qs = sm + FQ_OFF;

    const int tid = threadIdx.x;
    const int lane = tid & 31;
    const int wid = tid >> 5;        // 0..7, 16 query rows each
    const int gid = lane >> 2;       // 0..7
    const int tig = lane & 3;        // 0..3

    const int qt = gridDim.x - 1 - blockIdx.x;  // heavy tiles first
    const int h = blockIdx.y, b = blockIdx.z;
    const int bhBase = ((b * NH + h) * NS) << 6;
    const float* Qg = g_q + bhBase;
    const float* Kg = g_k + bhBase;
    const float* Vg = g_v + bhBase;

    // prologue: async-load Q tile + K0 + V0 (group 0)
#pragma unroll
    for (int i = 0; i < 8; i++) {
        const int f4 = tid + i * 256;
        const int r = f4 >> 4, c4 = (f4 & 15) * 4;
        CP_ASYNC16(smaddr(&Qs[r * FQS + c4]),
                   &Qg[((qt * 128 + r) << 6) + c4]);
    }
#pragma unroll
    for (int i = 0; i < 4; i++) {
        const int f4 = tid + i * 256;
        const int r = f4 >> 4, c4 = (f4 & 15) * 4;
        CP_ASYNC16(smaddr(&sm[FK_OFF + r * FQS + c4]), &Kg[(r << 6) + c4]);
        CP_ASYNC16(smaddr(&sm[FV_OFF + r * FVS + c4]), &Vg[(r << 6) + c4]);
    }
    CP_COMMIT();

    float o[8][4] = {};
    float m0 = -1e30f, m1 = -1e30f, l0 = 0.0f, l1 = 0.0f;
    const int wBase = wid * 16;
    const int rowG0 = qt * 128 + wBase + gid;
    const int ktMax = 2 * qt + 1;

    for (int kt = 0; kt <= ktMax; kt++) {
        const int st = kt & 1;
        if (kt < ktMax) {
            float* Kn = sm + FK_OFF + (st ^ 1) * 64 * FQS;
            float* Vn = sm + FV_OFF + (st ^ 1) * 64 * FVS;
            const float* Kgn = Kg + (((kt + 1) * 64) << 6);
            const float* Vgn = Vg + (((kt + 1) * 64) << 6);
#pragma unroll
            for (int i = 0; i < 4; i++) {
                const int f4 = tid + i * 256;
                const int r = f4 >> 4, c4 = (f4 & 15) * 4;
                CP_ASYNC16(smaddr(&Kn[r * FQS + c4]), &Kgn[(r << 6) + c4]);
                CP_ASYNC16(smaddr(&Vn[r * FVS + c4]), &Vgn[(r << 6) + c4]);
            }
            CP_COMMIT();
            CP_WAIT(1);
        } else {
            CP_WAIT(0);
        }
        __syncthreads();

        const float* Ks = sm + FK_OFF + st * 64 * FQS;
        const float* Vs = sm + FV_OFF + st * 64 * FVS;

        // Warp-level skip: rows of this warp all above the key range -> masked
        const bool active = (qt * 128 + wBase + 15) >= kt * 64;
        if (active) {
            // ---- S = Q @ K^T ----
            float s[8][4] = {};
#pragma unroll
            for (int kb = 0; kb < 8; kb++) {
                float2 qlo = *(const float2*)&Qs[(wBase + gid) * FQS + kb * 8 + 2 * tig];
                float2 qhi = *(const float2*)&Qs[(wBase + gid + 8) * FQS + kb * 8 + 2 * tig];
                const unsigned a0 = __float_as_uint(qlo.x);
                const unsigned a1 = __float_as_uint(qhi.x);
                const unsigned a2 = __float_as_uint(qlo.y);
                const unsigned a3 = __float_as_uint(qhi.y);
#pragma unroll
                for (int nt = 0; nt < 8; nt++) {
                    float2 bb = *(const float2*)&Ks[(nt * 8 + gid) * FQS + kb * 8 + 2 * tig];
                    mma_tf32(s[nt], a0, a1, a2, a3,
                             __float_as_uint(bb.x), __float_as_uint(bb.y));
                }
            }

            // ---- causal mask (last two kt tiles only) ----
            if (kt >= 2 * qt) {
#pragma unroll
                for (int nt = 0; nt < 8; nt++) {
                    const int col = kt * 64 + nt * 8 + 2 * tig;
                    if (col > rowG0) s[nt][0] = -1e30f;
                    if (col + 1 > rowG0) s[nt][1] = -1e30f;
                    if (col > rowG0 + 8) s[nt][2] = -1e30f;
                    if (col + 1 > rowG0 + 8) s[nt][3] = -1e30f;
                }
            }

            // ---- online softmax (registers + quad shuffles) ----
            float mx0 = -1e30f, mx1 = -1e30f;
#pragma unroll
            for (int nt = 0; nt < 8; nt++) {
                mx0 = fmaxf(mx0, fmaxf(s[nt][0], s[nt][1]));
                mx1 = fmaxf(mx1, fmaxf(s[nt][2], s[nt][3]));
            }
            mx0 = fmaxf(mx0, __shfl_xor_sync(0xffffffffu, mx0, 1));
            mx0 = fmaxf(mx0, __shfl_xor_sync(0xffffffffu, mx0, 2));
            mx1 = fmaxf(mx1, __shfl_xor_sync(0xffffffffu, mx1, 1));
            mx1 = fmaxf(mx1, __shfl_xor_sync(0xffffffffu, mx1, 2));
            const float mn0 = fmaxf(m0, mx0);
            const float mn1 = fmaxf(m1, mx1);
            const float al0 = __expf(m0 - mn0);
            const float al1 = __expf(m1 - mn1);
            m0 = mn0; m1 = mn1;
            float sum0 = 0.0f, sum1 = 0.0f;
#pragma unroll
            for (int nt = 0; nt < 8; nt++) {
                float p0 = __expf(s[nt][0] - mn0);
                float p1 = __expf(s[nt][1] - mn0);
                float p2 = __expf(s[nt][2] - mn1);
                float p3 = __expf(s[nt][3] - mn1);
                sum0 += p0 + p1;
                sum1 += p2 + p3;
                s[nt][0] = f2tf32(p0);
                s[nt][1] = f2tf32(p1);
                s[nt][2] = f2tf32(p2);
                s[nt][3] = f2tf32(p3);
            }
            sum0 += __shfl_xor_sync(0xffffffffu, sum0, 1);
            sum0 += __shfl_xor_sync(0xffffffffu, sum0, 2);
            sum1 += __shfl_xor_sync(0xffffffffu, sum1, 1);
            sum1 += __shfl_xor_sync(0xffffffffu, sum1, 2);
            l0 = l0 * al0 + sum0;
            l1 = l1 * al1 + sum1;

            // ---- O = O*alpha + P @ V  (V plain [key][hd], scalar pair) ----
#pragma unroll
            for (int nt = 0; nt < 8; nt++) {
                o[nt][0] *= al0; o[nt][1] *= al0;
                o[nt][2] *= al1; o[nt][3] *= al1;
            }
#pragma unroll
            for (int kb = 0; kb < 8; kb++) {
                const unsigned a0 = __float_as_uint(s[kb][0]);
                const unsigned a1 = __float_as_uint(s[kb][2]);
                const unsigned a2 = __float_as_uint(s[kb][1]);
                const unsigned a3 = __float_as_uint(s[kb][3]);
                const float* vrow = &Vs[(kb * 8 + 2 * tig) * FVS];
#pragma unroll
                for (int nt = 0; nt < 8; nt++) {
                    const unsigned b0 = __float_as_uint(vrow[nt * 8 + gid]);
                    const unsigned b1 = __float_as_uint(vrow[FVS + nt * 8 + gid]);
                    mma_tf32(o[nt], a0, a1, a2, a3, b0, b1);
                }
            }
        }
        __syncthreads();
    }

    // ---- normalize, round, store ctx permk'd in [B,S,D] for out_proj ----
    const float i0 = 1.0f / l0;
    const float i1 = 1.0f / l1;
    const int colBase = (h << 6) + 2 * tig;
    float* row0 = &g_ctx[(size_t)(b * NS + rowG0) * ND];
    float* row1 = &g_ctx[(size_t)(b * NS + rowG0 + 8) * ND];
#pragma unroll
    for (int nt = 0; nt < 8; nt++) {
        const int c = colBase + nt * 8;
        row0[permk(c)] = f2tf32(o[nt][0] * i0);
        row0[permk(c + 1)] = f2tf32(o[nt][1] * i0);
        row1[permk(c)] = f2tf32(o[nt][2] * i1);
        row1[permk(c + 1)] = f2tf32(o[nt][3] * i1);
    }
}

extern "C" void kernel_launch(void* const* d_in, const int* in_sizes, int n_in,
                              void* d_out, int out_size) {
    const float* x = (const float*)d_in[0];
    const float* Wq = (const float*)d_in[1];
    const float* bq = (const float*)d_in[2];
    const float* Wk = (const float*)d_in[3];
    const float* bk = (const float*)d_in[4];
    const float* Wv = (const float*)d_in[5];
    const float* bv = (const float*)d_in[6];
    const float* Wo = (const float*)d_in[7];
    const float* bo = (const float*)d_in[8];
    float* out = (float*)d_out;

    cudaFuncSetAttribute(flash_attn_kernel,
                         cudaFuncAttributeMaxDynamicSharedMemorySize,
                         F_SMEM_BYTES);
    cudaFuncSetAttribute(qkv_proj_kernel,
                         cudaFuncAttributeMaxDynamicSharedMemorySize,
                         GEMM_SMEM_BYTES);
    cudaFuncSetAttribute(out_proj_kernel,
                         cudaFuncAttributeMaxDynamicSharedMemorySize,
                         GEMM_SMEM_BYTES);

    // Prep: round + permute x; transpose + round + permute all W
    round_x_kernel<<<MTOT * ND / 1024, 256>>>(x);
    dim3 gw(ND / 32, ND / 32, 4);
    round_w_kernel<<<gw, dim3(32, 8)>>>(Wq, Wk, Wv, Wo);

    dim3 g1(ND / 128, MTOT / 128, 3);
    qkv_proj_kernel<<<g1, 256, GEMM_SMEM_BYTES>>>(bq, bk, bv);

    dim3 g2(NS / 128, NH, NB);
    flash_attn_kernel<<<g2, 256, F_SMEM_BYTES>>>();

    dim3 g3(ND / 128, MTOT / 128);
    out_proj_kernel<<<g3, 256, GEMM_SMEM_BYTES>>>(bo, out);
}

// round 7
// speedup vs baseline: 4.0327x; 1.0434x over previous
#include <cuda_runtime.h>
#include <math.h>

#define NB 2
#define NS 2048
#define ND 1024
#define NH 16
#define NHD 64
#define MTOT (NB * NS)   // 4096

// Scratch (allocation-free rule: __device__ globals)
__device__ float g_q[NB * NH * NS * NHD];    // [B,H,S,HD]
__device__ float g_k[NB * NH * NS * NHD];    // [B,H,S,HD]
__device__ float g_v[NB * NH * NHD * NS];    // [B,H,HD,S]  (transposed!)
__device__ float g_ctx[NB * NS * ND];        // tf32-rounded, permk'd columns
__device__ float g_xr[MTOT * ND];            // x, tf32-rounded, permk'd columns
__device__ float g_wr[4][ND * ND];           // W^T, tf32-rounded, permk'd cols

// ---------------------------------------------------------------------------
// helpers
// ---------------------------------------------------------------------------
__device__ __forceinline__ float f2tf32(float x) {
    unsigned r;
    asm("cvt.rna.tf32.f32 %0, %1;" : "=r"(r) : "f"(x));
    return __uint_as_float(r);
}

__device__ __forceinline__ void mma_tf32(float (&c)[4], unsigned a0, unsigned a1,
                                         unsigned a2, unsigned a3, unsigned b0,
                                         unsigned b1) {
    asm volatile(
        "mma.sync.aligned.m16n8k8.row.col.f32.tf32.tf32.f32 "
        "{%0,%1,%2,%3}, {%4,%5,%6,%7}, {%8,%9}, {%0,%1,%2,%3};\n"
        : "+f"(c[0]), "+f"(c[1]), "+f"(c[2]), "+f"(c[3])
        : "r"(a0), "r"(a1), "r"(a2), "r"(a3), "r"(b0), "r"(b1));
}

__device__ __forceinline__ unsigned smaddr(const void* p) {
    return (unsigned)__cvta_generic_to_shared(p);
}
#define CP_ASYNC16(dst, src) \
    asm volatile("cp.async.cg.shared.global [%0], [%1], 16;\n" ::"r"(dst), "l"(src))
#define CP_COMMIT() asm volatile("cp.async.commit_group;\n")
#define CP_WAIT(n) asm volatile("cp.async.wait_group %0;\n" ::"n"(n))

// interleave k within 8-blocks so fragment pairs (k, k+4) are adjacent.
__device__ __forceinline__ int permk(int c) {
    return (c & ~7) | ((c & 3) << 1) | ((c >> 2) & 1);
}

// ---------------------------------------------------------------------------
// Prep kernels: tf32-round + permute (x) / transpose+round+permute (W)
// ---------------------------------------------------------------------------
__global__ void __launch_bounds__(256)
round_x_kernel(const float* __restrict__ x) {
    const int f4 = blockIdx.x * 256 + threadIdx.x;
    const int base = f4 * 4;
    float4 v = *(const float4*)&x[base];
    g_xr[permk(base + 0)] = f2tf32(v.x);
    g_xr[permk(base + 1)] = f2tf32(v.y);
    g_xr[permk(base + 2)] = f2tf32(v.z);
    g_xr[permk(base + 3)] = f2tf32(v.w);
}

__global__ void __launch_bounds__(256)
round_w_kernel(const float* __restrict__ Wq, const float* __restrict__ Wk,
               const float* __restrict__ Wv, const float* __restrict__ Wo) {
    __shared__ float t[32][33];
    const float* W;
    if (blockIdx.z == 0) W = Wq;
    else if (blockIdx.z == 1) W = Wk;
    else if (blockIdx.z == 2) W = Wv;
    else W = Wo;
    float* out = &g_wr[blockIdx.z][0];

    const int k0 = blockIdx.x * 32, n0 = blockIdx.y * 32;
    const int tx = threadIdx.x, ty = threadIdx.y;
#pragma unroll
    for (int i = 0; i < 4; i++)
        t[ty + i * 8][tx] = W[(size_t)(k0 + ty + i * 8) * ND + n0 + tx];
    __syncthreads();
#pragma unroll
    for (int i = 0; i < 4; i++)
        out[(size_t)(n0 + ty + i * 8) * ND + k0 + permk(tx)] =
            f2tf32(t[tx][ty + i * 8]);
}

// ---------------------------------------------------------------------------
// 128x128x32 TF32 GEMM tile, 2-stage cp.async pipeline.
// Dynamic smem: As[2][128][40] | Bs[2][128][40]  (80 KB)
// ---------------------------------------------------------------------------
#define GEMM_STG (128 * 40)
#define GEMM_SMEM_FLOATS (4 * GEMM_STG)
#define GEMM_SMEM_BYTES (GEMM_SMEM_FLOATS * 4)

__device__ __forceinline__ void sgemm_mma(const float* __restrict__ A,
                                          const float* __restrict__ Bt,
                                          float (&acc)[2][8][4]) {
    extern __shared__ float gsm[];
    float* AsBase = gsm;                 // 2 stages of 128x40
    float* BsBase = gsm + 2 * GEMM_STG;  // 2 stages of 128x40

    const int tid = threadIdx.x;
    const int lane = tid & 31;
    const int wid = tid >> 5;
    const int warpM = wid >> 1;
    const int warpN = wid & 1;
    const int gid = lane >> 2;
    const int tig = lane & 3;
    const int mBase = blockIdx.y * 128;
    const int nBase = blockIdx.x * 128;

    // prologue: stage 0
#pragma unroll
    for (int i = 0; i < 4; i++) {
        const int f4 = tid + i * 256;
        const int m = f4 >> 3, c4 = (f4 & 7) * 4;
        CP_ASYNC16(smaddr(&AsBase[m * 40 + c4]),
                   &A[(size_t)(mBase + m) * ND + c4]);
        CP_ASYNC16(smaddr(&BsBase[m * 40 + c4]),
                   &Bt[(size_t)(nBase + m) * ND + c4]);
    }
    CP_COMMIT();

    for (int k0 = 0; k0 < ND; k0 += 32) {
        const int st = (k0 >> 5) & 1;
        if (k0 + 32 < ND) {
            float* An = AsBase + (st ^ 1) * GEMM_STG;
            float* Bn = BsBase + (st ^ 1) * GEMM_STG;
#pragma unroll
            for (int i = 0; i < 4; i++) {
                const int f4 = tid + i * 256;
                const int m = f4 >> 3, c4 = (f4 & 7) * 4;
                CP_ASYNC16(smaddr(&An[m * 40 + c4]),
                           &A[(size_t)(mBase + m) * ND + k0 + 32 + c4]);
                CP_ASYNC16(smaddr(&Bn[m * 40 + c4]),
                           &Bt[(size_t)(nBase + m) * ND + k0 + 32 + c4]);
            }
            CP_COMMIT();
            CP_WAIT(1);
        } else {
            CP_WAIT(0);
        }
        __syncthreads();

        const float* As = AsBase + st * GEMM_STG;
        const float* Bs = BsBase + st * GEMM_STG;
#pragma unroll
        for (int ks = 0; ks < 32; ks += 8) {
            unsigned bf[8][2];
#pragma unroll
            for (int nt = 0; nt < 8; nt++) {
                float2 bb = *(const float2*)&Bs[(warpN * 64 + nt * 8 + gid) * 40 + ks + 2 * tig];
                bf[nt][0] = __float_as_uint(bb.x);
                bf[nt][1] = __float_as_uint(bb.y);
            }
#pragma unroll
            for (int mt = 0; mt < 2; mt++) {
                const int m = warpM * 32 + mt * 16;
                float2 lo = *(const float2*)&As[(m + gid) * 40 + ks + 2 * tig];
                float2 hi = *(const float2*)&As[(m + gid + 8) * 40 + ks + 2 * tig];
                const unsigned a0 = __float_as_uint(lo.x);
                const unsigned a1 = __float_as_uint(hi.x);
                const unsigned a2 = __float_as_uint(lo.y);
                const unsigned a3 = __float_as_uint(hi.y);
#pragma unroll
                for (int nt = 0; nt < 8; nt++)
                    mma_tf32(acc[mt][nt], a0, a1, a2, a3, bf[nt][0], bf[nt][1]);
            }
        }
        __syncthreads();
    }
}

// QKV projection. Q/K in [B,H,S,HD]; V stored TRANSPOSED [B,H,HD,S]. z=3.
__global__ void __launch_bounds__(256, 2)
qkv_proj_kernel(const float* __restrict__ bq, const float* __restrict__ bk,
                const float* __restrict__ bv) {
    const float* Bt;
    const float* bias;
    float sc;
    if (blockIdx.z == 0) { Bt = g_wr[0]; bias = bq; sc = 0.125f; }
    else if (blockIdx.z == 1) { Bt = g_wr[1]; bias = bk; sc = 1.0f; }
    else { Bt = g_wr[2]; bias = bv; sc = 1.0f; }

    float acc[2][8][4] = {};
    sgemm_mma(g_xr, Bt, acc);

    const int lane = threadIdx.x & 31;
    const int wid = threadIdx.x >> 5;
    const int warpM = wid >> 1, warpN = wid & 1;
    const int gid = lane >> 2, tig = lane & 3;
    const int mBase = blockIdx.y * 128, nBase = blockIdx.x * 128;

    if (blockIdx.z < 2) {
        float* out = (blockIdx.z == 0) ? g_q : g_k;
#pragma unroll
        for (int mt = 0; mt < 2; mt++) {
#pragma unroll
            for (int nt = 0; nt < 8; nt++) {
                const int c = nBase + warpN * 64 + nt * 8 + tig * 2;
                const int h = c >> 6, hd = c & 63;
                const float b0v = bias[c], b1v = bias[c + 1];
#pragma unroll
                for (int half = 0; half < 2; half++) {
                    const int r = mBase + warpM * 32 + mt * 16 + gid + half * 8;
                    const int b = r >> 11, s = r & 2047;
                    float2 val;
                    val.x = f2tf32((acc[mt][nt][half * 2 + 0] + b0v) * sc);
                    val.y = f2tf32((acc[mt][nt][half * 2 + 1] + b1v) * sc);
                    *(float2*)&out[(((b * NH + h) * NS + s) << 6) + hd] = val;
                }
            }
        }
    } else {
        // V: transposed store g_v[((b*NH+h)*NHD + hd)*NS + s]
#pragma unroll
        for (int mt = 0; mt < 2; mt++) {
#pragma unroll
            for (int nt = 0; nt < 8; nt++) {
                const int c = nBase + warpN * 64 + nt * 8 + tig * 2;
                const int h = c >> 6, hd = c & 63;
                const float b0v = bias[c], b1v = bias[c + 1];
#pragma unroll
                for (int half = 0; half < 2; half++) {
                    const int r = mBase + warpM * 32 + mt * 16 + gid + half * 8;
                    const int b = r >> 11, s = r & 2047;
                    float* base = &g_v[(size_t)((b * NH + h) * NHD + hd) * NS + s];
                    base[0] = f2tf32(acc[mt][nt][half * 2 + 0] + b0v);
                    base[NS] = f2tf32(acc[mt][nt][half * 2 + 1] + b1v);
                }
            }
        }
    }
}

// Output projection: out = ctx @ Wo + bo (ctx pre-rounded/permuted by flash)
__global__ void __launch_bounds__(256, 2)
out_proj_kernel(const float* __restrict__ bo, float* __restrict__ out) {
    float acc[2][8][4] = {};
    sgemm_mma(g_ctx, g_wr[3], acc);

    const int lane = threadIdx.x & 31;
    const int wid = threadIdx.x >> 5;
    const int warpM = wid >> 1, warpN = wid & 1;
    const int gid = lane >> 2, tig = lane & 3;
    const int mBase = blockIdx.y * 128, nBase = blockIdx.x * 128;

#pragma unroll
    for (int mt = 0; mt < 2; mt++) {
#pragma unroll
        for (int nt = 0; nt < 8; nt++) {
            const int c = nBase + warpN * 64 + nt * 8 + tig * 2;
            const float b0v = bo[c], b1v = bo[c + 1];
#pragma unroll
            for (int half = 0; half < 2; half++) {
                const int r = mBase + warpM * 32 + mt * 16 + gid + half * 8;
                float2 val;
                val.x = acc[mt][nt][half * 2 + 0] + b0v;
                val.y = acc[mt][nt][half * 2 + 1] + b1v;
                *(float2*)&out[(size_t)r * ND + c] = val;
            }
        }
    }
}

// ---------------------------------------------------------------------------
// FlashAttention-2, cp.async double-buffered K/V, register softmax.
// 128q/CTA, 64-key tiles. Q[128][72], K[2][64][72], Vt[2][64][72] (hd-major,
// loaded directly from transposed g_v). All fragments are LDS.64,
// conflict-free at stride 72. Smem = 27648 floats (110.6 KB), 2 CTAs/SM.
// ---------------------------------------------------------------------------
#define FQS 72
#define FQ_OFF 0
#define FK_OFF (128 * FQS)
#define FV_OFF (FK_OFF + 2 * 64 * FQS)
#define F_SMEM_FLOATS (FV_OFF + 2 * 64 * FQS)
#define F_SMEM_BYTES (F_SMEM_FLOATS * 4)

__global__ void __launch_bounds__(256, 2) flash_attn_kernel() {
    extern __shared__ float sm[];
    float* Qs = sm + FQ_OFF;

    const int tid = threadIdx.x;
    const int lane = tid & 31;
    const int wid = tid >> 5;        // 0..7, 16 query rows each
    const int gid = lane >> 2;       // 0..7
    const int tig = lane & 3;        // 0..3

    const int qt = gridDim.x - 1 - blockIdx.x;  // heavy tiles first
    const int h = blockIdx.y, b = blockIdx.z;
    const int bhBase = ((b * NH + h) * NS) << 6;
    const float* Qg = g_q + bhBase;
    const float* Kg = g_k + bhBase;
    const float* Vgt = g_v + bhBase;  // same flat offset: [HD][S] block

    // prologue: async-load Q tile + K0 + V0 (group 0)
#pragma unroll
    for (int i = 0; i < 8; i++) {
        const int f4 = tid + i * 256;
        const int r = f4 >> 4, c4 = (f4 & 15) * 4;
        CP_ASYNC16(smaddr(&Qs[r * FQS + c4]),
                   &Qg[((qt * 128 + r) << 6) + c4]);
    }
#pragma unroll
    for (int i = 0; i < 4; i++) {
        const int f4 = tid + i * 256;
        const int r = f4 >> 4, c4 = (f4 & 15) * 4;
        CP_ASYNC16(smaddr(&sm[FK_OFF + r * FQS + c4]), &Kg[(r << 6) + c4]);
        // Vt row r = head-dim r, columns = keys
        CP_ASYNC16(smaddr(&sm[FV_OFF + r * FQS + c4]), &Vgt[r * NS + c4]);
    }
    CP_COMMIT();

    float o[8][4] = {};
    float m0 = -1e30f, m1 = -1e30f, l0 = 0.0f, l1 = 0.0f;
    const int wBase = wid * 16;
    const int rowG0 = qt * 128 + wBase + gid;
    const int ktMax = 2 * qt + 1;

    for (int kt = 0; kt <= ktMax; kt++) {
        const int st = kt & 1;
        if (kt < ktMax) {
            float* Kn = sm + FK_OFF + (st ^ 1) * 64 * FQS;
            float* Vn = sm + FV_OFF + (st ^ 1) * 64 * FQS;
            const float* Kgn = Kg + (((kt + 1) * 64) << 6);
            const float* Vgn = Vgt + (kt + 1) * 64;
#pragma unroll
            for (int i = 0; i < 4; i++) {
                const int f4 = tid + i * 256;
                const int r = f4 >> 4, c4 = (f4 & 15) * 4;
                CP_ASYNC16(smaddr(&Kn[r * FQS + c4]), &Kgn[(r << 6) + c4]);
                CP_ASYNC16(smaddr(&Vn[r * FQS + c4]), &Vgn[r * NS + c4]);
            }
            CP_COMMIT();
            CP_WAIT(1);
        } else {
            CP_WAIT(0);
        }
        __syncthreads();

        const float* Ks = sm + FK_OFF + st * 64 * FQS;
        const float* Vs = sm + FV_OFF + st * 64 * FQS;

        // Warp-level skip: rows of this warp all above the key range -> masked
        const bool active = (qt * 128 + wBase + 15) >= kt * 64;
        if (active) {
            // ---- S = Q @ K^T ----
            float s[8][4] = {};
#pragma unroll
            for (int kb = 0; kb < 8; kb++) {
                float2 qlo = *(const float2*)&Qs[(wBase + gid) * FQS + kb * 8 + 2 * tig];
                float2 qhi = *(const float2*)&Qs[(wBase + gid + 8) * FQS + kb * 8 + 2 * tig];
                const unsigned a0 = __float_as_uint(qlo.x);
                const unsigned a1 = __float_as_uint(qhi.x);
                const unsigned a2 = __float_as_uint(qlo.y);
                const unsigned a3 = __float_as_uint(qhi.y);
#pragma unroll
                for (int nt = 0; nt < 8; nt++) {
                    float2 bb = *(const float2*)&Ks[(nt * 8 + gid) * FQS + kb * 8 + 2 * tig];
                    mma_tf32(s[nt], a0, a1, a2, a3,
                             __float_as_uint(bb.x), __float_as_uint(bb.y));
                }
            }

            // ---- causal mask (last two kt tiles only) ----
            if (kt >= 2 * qt) {
#pragma unroll
                for (int nt = 0; nt < 8; nt++) {
                    const int col = kt * 64 + nt * 8 + 2 * tig;
                    if (col > rowG0) s[nt][0] = -1e30f;
                    if (col + 1 > rowG0) s[nt][1] = -1e30f;
                    if (col > rowG0 + 8) s[nt][2] = -1e30f;
                    if (col + 1 > rowG0 + 8) s[nt][3] = -1e30f;
                }
            }

            // ---- online softmax (registers + quad shuffles) ----
            float mx0 = -1e30f, mx1 = -1e30f;
#pragma unroll
            for (int nt = 0; nt < 8; nt++) {
                mx0 = fmaxf(mx0, fmaxf(s[nt][0], s[nt][1]));
                mx1 = fmaxf(mx1, fmaxf(s[nt][2], s[nt][3]));
            }
            mx0 = fmaxf(mx0, __shfl_xor_sync(0xffffffffu, mx0, 1));
            mx0 = fmaxf(mx0, __shfl_xor_sync(0xffffffffu, mx0, 2));
            mx1 = fmaxf(mx1, __shfl_xor_sync(0xffffffffu, mx1, 1));
            mx1 = fmaxf(mx1, __shfl_xor_sync(0xffffffffu, mx1, 2));
            const float mn0 = fmaxf(m0, mx0);
            const float mn1 = fmaxf(m1, mx1);
            const float al0 = __expf(m0 - mn0);
            const float al1 = __expf(m1 - mn1);
            m0 = mn0; m1 = mn1;
            float sum0 = 0.0f, sum1 = 0.0f;
#pragma unroll
            for (int nt = 0; nt < 8; nt++) {
                float p0 = __expf(s[nt][0] - mn0);
                float p1 = __expf(s[nt][1] - mn0);
                float p2 = __expf(s[nt][2] - mn1);
                float p3 = __expf(s[nt][3] - mn1);
                sum0 += p0 + p1;
                sum1 += p2 + p3;
                s[nt][0] = f2tf32(p0);
                s[nt][1] = f2tf32(p1);
                s[nt][2] = f2tf32(p2);
                s[nt][3] = f2tf32(p3);
            }
            sum0 += __shfl_xor_sync(0xffffffffu, sum0, 1);
            sum0 += __shfl_xor_sync(0xffffffffu, sum0, 2);
            sum1 += __shfl_xor_sync(0xffffffffu, sum1, 1);
            sum1 += __shfl_xor_sync(0xffffffffu, sum1, 2);
            l0 = l0 * al0 + sum0;
            l1 = l1 * al1 + sum1;

            // ---- O = O*alpha + P @ V  (Vt[hd][key], float2 b-frags) ----
#pragma unroll
            for (int nt = 0; nt < 8; nt++) {
                o[nt][0] *= al0; o[nt][1] *= al0;
                o[nt][2] *= al1; o[nt][3] *= al1;
            }
#pragma unroll
            for (int kb = 0; kb < 8; kb++) {
                const unsigned a0 = __float_as_uint(s[kb][0]);
                const unsigned a1 = __float_as_uint(s[kb][2]);
                const unsigned a2 = __float_as_uint(s[kb][1]);
                const unsigned a3 = __float_as_uint(s[kb][3]);
#pragma unroll
                for (int nt = 0; nt < 8; nt++) {
                    float2 bb = *(const float2*)&Vs[(nt * 8 + gid) * FQS + kb * 8 + 2 * tig];
                    mma_tf32(o[nt], a0, a1, a2, a3,
                             __float_as_uint(bb.x), __float_as_uint(bb.y));
                }
            }
        }
        __syncthreads();
    }

    // ---- normalize, round, store ctx permk'd in [B,S,D] for out_proj ----
    const float i0 = 1.0f / l0;
    const float i1 = 1.0f / l1;
    const int colBase = (h << 6) + 2 * tig;
    float* row0 = &g_ctx[(size_t)(b * NS + rowG0) * ND];
    float* row1 = &g_ctx[(size_t)(b * NS + rowG0 + 8) * ND];
#pragma unroll
    for (int nt = 0; nt < 8; nt++) {
        const int c = colBase + nt * 8;
        row0[permk(c)] = f2tf32(o[nt][0] * i0);
        row0[permk(c + 1)] = f2tf32(o[nt][1] * i0);
        row1[permk(c)] = f2tf32(o[nt][2] * i1);
        row1[permk(c + 1)] = f2tf32(o[nt][3] * i1);
    }
}

extern "C" void kernel_launch(void* const* d_in, const int* in_sizes, int n_in,
                              void* d_out, int out_size) {
    const float* x = (const float*)d_in[0];
    const float* Wq = (const float*)d_in[1];
    const float* bq = (const float*)d_in[2];
    const float* Wk = (const float*)d_in[3];
    const float* bk = (const float*)d_in[4];
    const float* Wv = (const float*)d_in[5];
    const float* bv = (const float*)d_in[6];
    const float* Wo = (const float*)d_in[7];
    const float* bo = (const float*)d_in[8];
    float* out = (float*)d_out;

    cudaFuncSetAttribute(flash_attn_kernel,
                         cudaFuncAttributeMaxDynamicSharedMemorySize,
                         F_SMEM_BYTES);
    cudaFuncSetAttribute(qkv_proj_kernel,
                         cudaFuncAttributeMaxDynamicSharedMemorySize,
                         GEMM_SMEM_BYTES);
    cudaFuncSetAttribute(out_proj_kernel,
                         cudaFuncAttributeMaxDynamicSharedMemorySize,
                         GEMM_SMEM_BYTES);

    // Prep: round + permute x; transpose + round + permute all W
    round_x_kernel<<<MTOT * ND / 1024, 256>>>(x);
    dim3 gw(ND / 32, ND / 32, 4);
    round_w_kernel<<<gw, dim3(32, 8)>>>(Wq, Wk, Wv, Wo);

    dim3 g1(ND / 128, MTOT / 128, 3);
    qkv_proj_kernel<<<g1, 256, GEMM_SMEM_BYTES>>>(bq, bk, bv);

    dim3 g2(NS / 128, NH, NB);
    flash_attn_kernel<<<g2, 256, F_SMEM_BYTES>>>();

    dim3 g3(ND / 128, MTOT / 128);
    out_proj_kernel<<<g3, 256, GEMM_SMEM_BYTES>>>(bo, out);
}

// round 8
// speedup vs baseline: 4.2749x; 1.0601x over previous
#include <cuda_runtime.h>
#include <math.h>

#define NB 2
#define NS 2048
#define ND 1024
#define NH 16
#define NHD 64
#define MTOT (NB * NS)   // 4096

// Scratch (allocation-free rule: __device__ globals)
__device__ float g_q[NB * NH * NS * NHD];    // [B,H,S,HD]
__device__ float g_k[NB * NH * NS * NHD];    // [B,H,S,HD]
__device__ float g_v[NB * NH * NHD * NS];    // [B,H,HD,S]  (transposed!)
__device__ float g_ctx[NB * NS * ND];        // tf32-rounded, permk'd columns
__device__ float g_xr[MTOT * ND];            // x, tf32-rounded, permk'd columns
__device__ float g_wr[4][ND * ND];           // W^T, tf32-rounded, permk'd cols

// ---------------------------------------------------------------------------
// helpers
// ---------------------------------------------------------------------------
__device__ __forceinline__ float f2tf32(float x) {
    unsigned r;
    asm("cvt.rna.tf32.f32 %0, %1;" : "=r"(r) : "f"(x));
    return __uint_as_float(r);
}

__device__ __forceinline__ void mma_tf32(float (&c)[4], unsigned a0, unsigned a1,
                                         unsigned a2, unsigned a3, unsigned b0,
                                         unsigned b1) {
    asm volatile(
        "mma.sync.aligned.m16n8k8.row.col.f32.tf32.tf32.f32 "
        "{%0,%1,%2,%3}, {%4,%5,%6,%7}, {%8,%9}, {%0,%1,%2,%3};\n"
        : "+f"(c[0]), "+f"(c[1]), "+f"(c[2]), "+f"(c[3])
        : "r"(a0), "r"(a1), "r"(a2), "r"(a3), "r"(b0), "r"(b1));
}

__device__ __forceinline__ unsigned smaddr(const void* p) {
    return (unsigned)__cvta_generic_to_shared(p);
}
#define CP_ASYNC16(dst, src) \
    asm volatile("cp.async.cg.shared.global [%0], [%1], 16;\n" ::"r"(dst), "l"(src))
#define CP_COMMIT() asm volatile("cp.async.commit_group;\n")
#define CP_WAIT(n) asm volatile("cp.async.wait_group %0;\n" ::"n"(n))

// interleave k within 8-blocks so fragment pairs (k, k+4) are adjacent.
__device__ __forceinline__ int permk(int c) {
    return (c & ~7) | ((c & 3) << 1) | ((c >> 2) & 1);
}

// ---------------------------------------------------------------------------
// Prep kernels: tf32-round + permute (x) / transpose+round+permute (W)
// ---------------------------------------------------------------------------
__global__ void __launch_bounds__(256)
round_x_kernel(const float* __restrict__ x) {
    const int f4 = blockIdx.x * 256 + threadIdx.x;
    const int base = f4 * 4;
    float4 v = *(const float4*)&x[base];
    g_xr[permk(base + 0)] = f2tf32(v.x);
    g_xr[permk(base + 1)] = f2tf32(v.y);
    g_xr[permk(base + 2)] = f2tf32(v.z);
    g_xr[permk(base + 3)] = f2tf32(v.w);
}

__global__ void __launch_bounds__(256)
round_w_kernel(const float* __restrict__ Wq, const float* __restrict__ Wk,
               const float* __restrict__ Wv, const float* __restrict__ Wo) {
    __shared__ float t[32][33];
    const float* W;
    if (blockIdx.z == 0) W = Wq;
    else if (blockIdx.z == 1) W = Wk;
    else if (blockIdx.z == 2) W = Wv;
    else W = Wo;
    float* out = &g_wr[blockIdx.z][0];

    const int k0 = blockIdx.x * 32, n0 = blockIdx.y * 32;
    const int tx = threadIdx.x, ty = threadIdx.y;
#pragma unroll
    for (int i = 0; i < 4; i++)
        t[ty + i * 8][tx] = W[(size_t)(k0 + ty + i * 8) * ND + n0 + tx];
    __syncthreads();
#pragma unroll
    for (int i = 0; i < 4; i++)
        out[(size_t)(n0 + ty + i * 8) * ND + k0 + permk(tx)] =
            f2tf32(t[tx][ty + i * 8]);
}

// ---------------------------------------------------------------------------
// 256x128x32 TF32 GEMM tile, 2-stage cp.async pipeline, 1 CTA/SM.
// 8 warps in 4(M) x 2(N); warp tile 64x64 = 4x8 m16n8k8 atoms (128 acc regs).
// Dynamic smem: As[2][256][40] | Bs[2][128][40]  (122.9 KB)
// ---------------------------------------------------------------------------
#define GEMM_ASTG (256 * 40)
#define GEMM_BSTG (128 * 40)
#define GEMM_SMEM_FLOATS (2 * GEMM_ASTG + 2 * GEMM_BSTG)
#define GEMM_SMEM_BYTES (GEMM_SMEM_FLOATS * 4)

__device__ __forceinline__ void sgemm_mma(const float* __restrict__ A,
                                          const float* __restrict__ Bt,
                                          float (&acc)[4][8][4]) {
    extern __shared__ float gsm[];
    float* AsBase = gsm;                   // 2 stages of 256x40
    float* BsBase = gsm + 2 * GEMM_ASTG;   // 2 stages of 128x40

    const int tid = threadIdx.x;
    const int lane = tid & 31;
    const int wid = tid >> 5;
    const int warpM = wid >> 1;   // 0..3 -> 64 rows each
    const int warpN = wid & 1;    // 0..1 -> 64 cols each
    const int gid = lane >> 2;
    const int tig = lane & 3;
    const int mBase = blockIdx.y * 256;
    const int nBase = blockIdx.x * 128;

    // prologue: stage 0
#pragma unroll
    for (int i = 0; i < 8; i++) {
        const int f4 = tid + i * 256;
        const int m = f4 >> 3, c4 = (f4 & 7) * 4;
        CP_ASYNC16(smaddr(&AsBase[m * 40 + c4]),
                   &A[(size_t)(mBase + m) * ND + c4]);
    }
#pragma unroll
    for (int i = 0; i < 4; i++) {
        const int f4 = tid + i * 256;
        const int m = f4 >> 3, c4 = (f4 & 7) * 4;
        CP_ASYNC16(smaddr(&BsBase[m * 40 + c4]),
                   &Bt[(size_t)(nBase + m) * ND + c4]);
    }
    CP_COMMIT();

    for (int k0 = 0; k0 < ND; k0 += 32) {
        const int st = (k0 >> 5) & 1;
        if (k0 + 32 < ND) {
            float* An = AsBase + (st ^ 1) * GEMM_ASTG;
            float* Bn = BsBase + (st ^ 1) * GEMM_BSTG;
#pragma unroll
            for (int i = 0; i < 8; i++) {
                const int f4 = tid + i * 256;
                const int m = f4 >> 3, c4 = (f4 & 7) * 4;
                CP_ASYNC16(smaddr(&An[m * 40 + c4]),
                           &A[(size_t)(mBase + m) * ND + k0 + 32 + c4]);
            }
#pragma unroll
            for (int i = 0; i < 4; i++) {
                const int f4 = tid + i * 256;
                const int m = f4 >> 3, c4 = (f4 & 7) * 4;
                CP_ASYNC16(smaddr(&Bn[m * 40 + c4]),
                           &Bt[(size_t)(nBase + m) * ND + k0 + 32 + c4]);
            }
            CP_COMMIT();
            CP_WAIT(1);
        } else {
            CP_WAIT(0);
        }
        __syncthreads();

        const float* As = AsBase + st * GEMM_ASTG;
        const float* Bs = BsBase + st * GEMM_BSTG;
#pragma unroll
        for (int ks = 0; ks < 32; ks += 8) {
            unsigned bf[8][2];
#pragma unroll
            for (int nt = 0; nt < 8; nt++) {
                float2 bb = *(const float2*)&Bs[(warpN * 64 + nt * 8 + gid) * 40 + ks + 2 * tig];
                bf[nt][0] = __float_as_uint(bb.x);
                bf[nt][1] = __float_as_uint(bb.y);
            }
#pragma unroll
            for (int mt = 0; mt < 4; mt++) {
                const int m = warpM * 64 + mt * 16;
                float2 lo = *(const float2*)&As[(m + gid) * 40 + ks + 2 * tig];
                float2 hi = *(const float2*)&As[(m + gid + 8) * 40 + ks + 2 * tig];
                const unsigned a0 = __float_as_uint(lo.x);
                const unsigned a1 = __float_as_uint(hi.x);
                const unsigned a2 = __float_as_uint(lo.y);
                const unsigned a3 = __float_as_uint(hi.y);
#pragma unroll
                for (int nt = 0; nt < 8; nt++)
                    mma_tf32(acc[mt][nt], a0, a1, a2, a3, bf[nt][0], bf[nt][1]);
            }
        }
        __syncthreads();
    }
}

// QKV projection. Q/K in [B,H,S,HD]; V stored TRANSPOSED [B,H,HD,S]. z=3.
__global__ void __launch_bounds__(256, 1)
qkv_proj_kernel(const float* __restrict__ bq, const float* __restrict__ bk,
                const float* __restrict__ bv) {
    const float* Bt;
    const float* bias;
    float sc;
    if (blockIdx.z == 0) { Bt = g_wr[0]; bias = bq; sc = 0.125f; }
    else if (blockIdx.z == 1) { Bt = g_wr[1]; bias = bk; sc = 1.0f; }
    else { Bt = g_wr[2]; bias = bv; sc = 1.0f; }

    float acc[4][8][4] = {};
    sgemm_mma(g_xr, Bt, acc);

    const int lane = threadIdx.x & 31;
    const int wid = threadIdx.x >> 5;
    const int warpM = wid >> 1, warpN = wid & 1;
    const int gid = lane >> 2, tig = lane & 3;
    const int mBase = blockIdx.y * 256, nBase = blockIdx.x * 128;

    if (blockIdx.z < 2) {
        float* out = (blockIdx.z == 0) ? g_q : g_k;
#pragma unroll
        for (int mt = 0; mt < 4; mt++) {
#pragma unroll
            for (int nt = 0; nt < 8; nt++) {
                const int c = nBase + warpN * 64 + nt * 8 + tig * 2;
                const int h = c >> 6, hd = c & 63;
                const float b0v = bias[c], b1v = bias[c + 1];
#pragma unroll
                for (int half = 0; half < 2; half++) {
                    const int r = mBase + warpM * 64 + mt * 16 + gid + half * 8;
                    const int b = r >> 11, s = r & 2047;
                    float2 val;
                    val.x = f2tf32((acc[mt][nt][half * 2 + 0] + b0v) * sc);
                    val.y = f2tf32((acc[mt][nt][half * 2 + 1] + b1v) * sc);
                    *(float2*)&out[(((b * NH + h) * NS + s) << 6) + hd] = val;
                }
            }
        }
    } else {
        // V: transposed store g_v[((b*NH+h)*NHD + hd)*NS + s]
#pragma unroll
        for (int mt = 0; mt < 4; mt++) {
#pragma unroll
            for (int nt = 0; nt < 8; nt++) {
                const int c = nBase + warpN * 64 + nt * 8 + tig * 2;
                const int h = c >> 6, hd = c & 63;
                const float b0v = bias[c], b1v = bias[c + 1];
#pragma unroll
                for (int half = 0; half < 2; half++) {
                    const int r = mBase + warpM * 64 + mt * 16 + gid + half * 8;
                    const int b = r >> 11, s = r & 2047;
                    float* base = &g_v[(size_t)((b * NH + h) * NHD + hd) * NS + s];
                    base[0] = f2tf32(acc[mt][nt][half * 2 + 0] + b0v);
                    base[NS] = f2tf32(acc[mt][nt][half * 2 + 1] + b1v);
                }
            }
        }
    }
}

// Output projection: out = ctx @ Wo + bo (ctx pre-rounded/permuted by flash)
__global__ void __launch_bounds__(256, 1)
out_proj_kernel(const float* __restrict__ bo, float* __restrict__ out) {
    float acc[4][8][4] = {};
    sgemm_mma(g_ctx, g_wr[3], acc);

    const int lane = threadIdx.x & 31;
    const int wid = threadIdx.x >> 5;
    const int warpM = wid >> 1, warpN = wid & 1;
    const int gid = lane >> 2, tig = lane & 3;
    const int mBase = blockIdx.y * 256, nBase = blockIdx.x * 128;

#pragma unroll
    for (int mt = 0; mt < 4; mt++) {
#pragma unroll
        for (int nt = 0; nt < 8; nt++) {
            const int c = nBase + warpN * 64 + nt * 8 + tig * 2;
            const float b0v = bo[c], b1v = bo[c + 1];
#pragma unroll
            for (int half = 0; half < 2; half++) {
                const int r = mBase + warpM * 64 + mt * 16 + gid + half * 8;
                float2 val;
                val.x = acc[mt][nt][half * 2 + 0] + b0v;
                val.y = acc[mt][nt][half * 2 + 1] + b1v;
                *(float2*)&out[(size_t)r * ND + c] = val;
            }
        }
    }
}

// ---------------------------------------------------------------------------
// FlashAttention-2, cp.async double-buffered K/V, register softmax.
// (unchanged from round 7 — known good)
// ---------------------------------------------------------------------------
#define FQS 72
#define FQ_OFF 0
#define FK_OFF (128 * FQS)
#define FV_OFF (FK_OFF + 2 * 64 * FQS)
#define F_SMEM_FLOATS (FV_OFF + 2 * 64 * FQS)
#define F_SMEM_BYTES (F_SMEM_FLOATS * 4)

__global__ void __launch_bounds__(256, 2) flash_attn_kernel() {
    extern __shared__ float sm[];
    float* Qs = sm + FQ_OFF;

    const int tid = threadIdx.x;
    const int lane = tid & 31;
    const int wid = tid >> 5;        // 0..7, 16 query rows each
    const int gid = lane >> 2;       // 0..7
    const int tig = lane & 3;        // 0..3

    const int qt = gridDim.x - 1 - blockIdx.x;  // heavy tiles first
    const int h = blockIdx.y, b = blockIdx.z;
    const int bhBase = ((b * NH + h) * NS) << 6;
    const float* Qg = g_q + bhBase;
    const float* Kg = g_k + bhBase;
    const float* Vgt = g_v + bhBase;  // same flat offset: [HD][S] block

    // prologue: async-load Q tile + K0 + V0 (group 0)
#pragma unroll
    for (int i = 0; i < 8; i++) {
        const int f4 = tid + i * 256;
        const int r = f4 >> 4, c4 = (f4 & 15) * 4;
        CP_ASYNC16(smaddr(&Qs[r * FQS + c4]),
                   &Qg[((qt * 128 + r) << 6) + c4]);
    }
#pragma unroll
    for (int i = 0; i < 4; i++) {
        const int f4 = tid + i * 256;
        const int r = f4 >> 4, c4 = (f4 & 15) * 4;
        CP_ASYNC16(smaddr(&sm[FK_OFF + r * FQS + c4]), &Kg[(r << 6) + c4]);
        CP_ASYNC16(smaddr(&sm[FV_OFF + r * FQS + c4]), &Vgt[r * NS + c4]);
    }
    CP_COMMIT();

    float o[8][4] = {};
    float m0 = -1e30f, m1 = -1e30f, l0 = 0.0f, l1 = 0.0f;
    const int wBase = wid * 16;
    const int rowG0 = qt * 128 + wBase + gid;
    const int ktMax = 2 * qt + 1;

    for (int kt = 0; kt <= ktMax; kt++) {
        const int st = kt & 1;
        if (kt < ktMax) {
            float* Kn = sm + FK_OFF + (st ^ 1) * 64 * FQS;
            float* Vn = sm + FV_OFF + (st ^ 1) * 64 * FQS;
            const float* Kgn = Kg + (((kt + 1) * 64) << 6);
            const float* Vgn = Vgt + (kt + 1) * 64;
#pragma unroll
            for (int i = 0; i < 4; i++) {
                const int f4 = tid + i * 256;
                const int r = f4 >> 4, c4 = (f4 & 15) * 4;
                CP_ASYNC16(smaddr(&Kn[r * FQS + c4]), &Kgn[(r << 6) + c4]);
                CP_ASYNC16(smaddr(&Vn[r * FQS + c4]), &Vgn[r * NS + c4]);
            }
            CP_COMMIT();
            CP_WAIT(1);
        } else {
            CP_WAIT(0);
        }
        __syncthreads();

        const float* Ks = sm + FK_OFF + st * 64 * FQS;
        const float* Vs = sm + FV_OFF + st * 64 * FQS;

        // Warp-level skip: rows of this warp all above the key range -> masked
        const bool active = (qt * 128 + wBase + 15) >= kt * 64;
        if (active) {
            // ---- S = Q @ K^T ----
            float s[8][4] = {};
#pragma unroll
            for (int kb = 0; kb < 8; kb++) {
                float2 qlo = *(const float2*)&Qs[(wBase + gid) * FQS + kb * 8 + 2 * tig];
                float2 qhi = *(const float2*)&Qs[(wBase + gid + 8) * FQS + kb * 8 + 2 * tig];
                const unsigned a0 = __float_as_uint(qlo.x);
                const unsigned a1 = __float_as_uint(qhi.x);
                const unsigned a2 = __float_as_uint(qlo.y);
                const unsigned a3 = __float_as_uint(qhi.y);
#pragma unroll
                for (int nt = 0; nt < 8; nt++) {
                    float2 bb = *(const float2*)&Ks[(nt * 8 + gid) * FQS + kb * 8 + 2 * tig];
                    mma_tf32(s[nt], a0, a1, a2, a3,
                             __float_as_uint(bb.x), __float_as_uint(bb.y));
                }
            }

            // ---- causal mask (last two kt tiles only) ----
            if (kt >= 2 * qt) {
#pragma unroll
                for (int nt = 0; nt < 8; nt++) {
                    const int col = kt * 64 + nt * 8 + 2 * tig;
                    if (col > rowG0) s[nt][0] = -1e30f;
                    if (col + 1 > rowG0) s[nt][1] = -1e30f;
                    if (col > rowG0 + 8) s[nt][2] = -1e30f;
                    if (col + 1 > rowG0 + 8) s[nt][3] = -1e30f;
                }
            }

            // ---- online softmax (registers + quad shuffles) ----
            float mx0 = -1e30f, mx1 = -1e30f;
#pragma unroll
            for (int nt = 0; nt < 8; nt++) {
                mx0 = fmaxf(mx0, fmaxf(s[nt][0], s[nt][1]));
                mx1 = fmaxf(mx1, fmaxf(s[nt][2], s[nt][3]));
            }
            mx0 = fmaxf(mx0, __shfl_xor_sync(0xffffffffu, mx0, 1));
            mx0 = fmaxf(mx0, __shfl_xor_sync(0xffffffffu, mx0, 2));
            mx1 = fmaxf(mx1, __shfl_xor_sync(0xffffffffu, mx1, 1));
            mx1 = fmaxf(mx1, __shfl_xor_sync(0xffffffffu, mx1, 2));
            const float mn0 = fmaxf(m0, mx0);
            const float mn1 = fmaxf(m1, mx1);
            const float al0 = __expf(m0 - mn0);
            const float al1 = __expf(m1 - mn1);
            m0 = mn0; m1 = mn1;
            float sum0 = 0.0f, sum1 = 0.0f;
#pragma unroll
            for (int nt = 0; nt < 8; nt++) {
                float p0 = __expf(s[nt][0] - mn0);
                float p1 = __expf(s[nt][1] - mn0);
                float p2 = __expf(s[nt][2] - mn1);
                float p3 = __expf(s[nt][3] - mn1);
                sum0 += p0 + p1;
                sum1 += p2 + p3;
                s[nt][0] = f2tf32(p0);
                s[nt][1] = f2tf32(p1);
                s[nt][2] = f2tf32(p2);
                s[nt][3] = f2tf32(p3);
            }
            sum0 += __shfl_xor_sync(0xffffffffu, sum0, 1);
            sum0 += __shfl_xor_sync(0xffffffffu, sum0, 2);
            sum1 += __shfl_xor_sync(0xffffffffu, sum1, 1);
            sum1 += __shfl_xor_sync(0xffffffffu, sum1, 2);
            l0 = l0 * al0 + sum0;
            l1 = l1 * al1 + sum1;

            // ---- O = O*alpha + P @ V  (Vt[hd][key], float2 b-frags) ----
#pragma unroll
            for (int nt = 0; nt < 8; nt++) {
                o[nt][0] *= al0; o[nt][1] *= al0;
                o[nt][2] *= al1; o[nt][3] *= al1;
            }
#pragma unroll
            for (int kb = 0; kb < 8; kb++) {
                const unsigned a0 = __float_as_uint(s[kb][0]);
                const unsigned a1 = __float_as_uint(s[kb][2]);
                const unsigned a2 = __float_as_uint(s[kb][1]);
                const unsigned a3 = __float_as_uint(s[kb][3]);
#pragma unroll
                for (int nt = 0; nt < 8; nt++) {
                    float2 bb = *(const float2*)&Vs[(nt * 8 + gid) * FQS + kb * 8 + 2 * tig];
                    mma_tf32(o[nt], a0, a1, a2, a3,
                             __float_as_uint(bb.x), __float_as_uint(bb.y));
                }
            }
        }
        __syncthreads();
    }

    // ---- normalize, round, store ctx permk'd in [B,S,D] for out_proj ----
    const float i0 = 1.0f / l0;
    const float i1 = 1.0f / l1;
    const int colBase = (h << 6) + 2 * tig;
    float* row0 = &g_ctx[(size_t)(b * NS + rowG0) * ND];
    float* row1 = &g_ctx[(size_t)(b * NS + rowG0 + 8) * ND];
#pragma unroll
    for (int nt = 0; nt < 8; nt++) {
        const int c = colBase + nt * 8;
        row0[permk(c)] = f2tf32(o[nt][0] * i0);
        row0[permk(c + 1)] = f2tf32(o[nt][1] * i0);
        row1[permk(c)] = f2tf32(o[nt][2] * i1);
        row1[permk(c + 1)] = f2tf32(o[nt][3] * i1);
    }
}

extern "C" void kernel_launch(void* const* d_in, const int* in_sizes, int n_in,
                              void* d_out, int out_size) {
    const float* x = (const float*)d_in[0];
    const float* Wq = (const float*)d_in[1];
    const float* bq = (const float*)d_in[2];
    const float* Wk = (const float*)d_in[3];
    const float* bk = (const float*)d_in[4];
    const float* Wv = (const float*)d_in[5];
    const float* bv = (const float*)d_in[6];
    const float* Wo = (const float*)d_in[7];
    const float* bo = (const float*)d_in[8];
    float* out = (float*)d_out;

    cudaFuncSetAttribute(flash_attn_kernel,
                         cudaFuncAttributeMaxDynamicSharedMemorySize,
                         F_SMEM_BYTES);
    cudaFuncSetAttribute(qkv_proj_kernel,
                         cudaFuncAttributeMaxDynamicSharedMemorySize,
                         GEMM_SMEM_BYTES);
    cudaFuncSetAttribute(out_proj_kernel,
                         cudaFuncAttributeMaxDynamicSharedMemorySize,
                         GEMM_SMEM_BYTES);

    // Prep: round + permute x; transpose + round + permute all W
    round_x_kernel<<<MTOT * ND / 1024, 256>>>(x);
    dim3 gw(ND / 32, ND / 32, 4);
    round_w_kernel<<<gw, dim3(32, 8)>>>(Wq, Wk, Wv, Wo);

    dim3 g1(ND / 128, MTOT / 256, 3);
    qkv_proj_kernel<<<g1, 256, GEMM_SMEM_BYTES>>>(bq, bk, bv);

    dim3 g2(NS / 128, NH, NB);
    flash_attn_kernel<<<g2, 256, F_SMEM_BYTES>>>();

    dim3 g3(ND / 128, MTOT / 256);
    out_proj_kernel<<<g3, 256, GEMM_SMEM_BYTES>>>(bo, out);
}